// round 1
// baseline (speedup 1.0000x reference)
#include <cuda_runtime.h>
#include <cstdint>

#define BB 1024
#define VV 8
#define NDm 32
#define NPm 16
#define NMm 24
#define DD 256
#define VOC_D 2000
#define VOC_P 1500
#define VOC_M 131

// ---------------- scratch layout (floats) ----------------
#define OFF_HED   0L
#define OFF_HEP   512000L
#define OFF_HEM   896000L
#define OFF_TEMD  929536L
#define OFF_TEMP  963072L
#define OFF_TEDM  996608L
#define OFF_TEPM  1508608L
#define OFF_SEQ   1892608L        // [3][8192][256]
#define OFF_GI    8184064L        // [3][8192][768]
#define OFF_H     27058432L       // [3][1024][256]
#define OFF_GH    27844864L       // [3][1024][768]
#define OFF_HR    30204160L       // [1024][768]
#define OFF_WQ2   30990592L       // [256][768]
#define OFF_BQP   31187200L       // [256]
#define OFF_SP    31187456L       // [1024][256]
#define OFF_PART  31449600L       // [1024]
#define SCRATCH_TOTAL 31450624L

__device__ __align__(256) float g_scratch[SCRATCH_TOTAL];

__device__ __forceinline__ float dot4(float4 a, float4 b) {
    return a.x*b.x + a.y*b.y + a.z*b.z + a.w*b.w;
}
__device__ __forceinline__ float sigm(float x) { return 1.0f / (1.0f + expf(-x)); }

// ---------------- Kernel: table precompute  dst[r] = E[r] @ W  ----------------
// block = 256 threads, handles 8 rows
__global__ __launch_bounds__(256) void table_kernel(
    const float* __restrict__ E, const float* __restrict__ W,
    float* __restrict__ dst, int rows)
{
    __shared__ float e[8][DD];
    int tid = threadIdx.x;
    int r0 = blockIdx.x * 8;
#pragma unroll
    for (int i = 0; i < 8; i++)
        e[i][tid] = (r0 + i < rows) ? E[(long)(r0 + i) * DD + tid] : 0.0f;
    __syncthreads();
    float acc[8] = {0,0,0,0,0,0,0,0};
#pragma unroll 4
    for (int k = 0; k < DD; k++) {
        float w = W[(long)k * DD + tid];
#pragma unroll
        for (int i = 0; i < 8; i++) acc[i] += e[i][k] * w;
    }
#pragma unroll
    for (int i = 0; i < 8; i++)
        if (r0 + i < rows) dst[(long)(r0 + i) * DD + tid] = acc[i];
}

// ---------------- Kernel: Wq2 build ----------------
__global__ void wq2_kernel(const float* __restrict__ Wq, const float* __restrict__ bq,
                           float* __restrict__ Wq2p, float* __restrict__ bqp)
{
    int j = blockIdx.x;       // 0..255
    int tid = threadIdx.x;    // 256
    for (int c = tid; c < 768; c += 256) {
        float v = 0.0f;
        if (j < VOC_M) v = Wq[(long)j * 1536 + c] + Wq[(long)j * 1536 + 768 + c];
        Wq2p[(long)j * 768 + c] = v;
    }
    if (tid == 0) bqp[j] = (j < VOC_M) ? bq[j] : 0.0f;
}

// ---------------- per-(b,v) fused graph kernel ----------------
#define HP 260   // padded row stride for h buffer (260*4 bytes, 16B aligned)

__device__ float homo_phase(const float* __restrict__ table, const int* sidx,
                            const float* __restrict__ adjg, int N,
                            float* hbuf, float* Sbuf, float* abuf, float* csm, int tid)
{
    // gather h rows
    for (int r = 0; r < N; r++)
        hbuf[r * HP + tid] = table[(long)sidx[r] * DD + tid];
    // load adj
    for (int i = tid; i < N * N; i += 256)
        abuf[(i / N) * 33 + (i % N)] = adjg[i];
    __syncthreads();

    // S = h h^T / 16 : 2x2 register tiles
    int half = N >> 1;
    if (tid < half * half) {
        int tn = tid / half, tm = tid % half;
        const float* A0 = &hbuf[(2 * tn) * HP];
        const float* A1 = A0 + HP;
        const float* B0 = &hbuf[(2 * tm) * HP];
        const float* B1 = B0 + HP;
        float s00 = 0, s01 = 0, s10 = 0, s11 = 0;
#pragma unroll 4
        for (int k = 0; k < DD; k += 4) {
            float4 a0 = *(const float4*)(A0 + k);
            float4 a1 = *(const float4*)(A1 + k);
            float4 b0 = *(const float4*)(B0 + k);
            float4 b1 = *(const float4*)(B1 + k);
            s00 += dot4(a0, b0); s01 += dot4(a0, b1);
            s10 += dot4(a1, b0); s11 += dot4(a1, b1);
        }
        Sbuf[(2 * tn) * 33 + 2 * tm]         = s00 * 0.0625f;
        Sbuf[(2 * tn) * 33 + 2 * tm + 1]     = s01 * 0.0625f;
        Sbuf[(2 * tn + 1) * 33 + 2 * tm]     = s10 * 0.0625f;
        Sbuf[(2 * tn + 1) * 33 + 2 * tm + 1] = s11 * 0.0625f;
    }
    __syncthreads();

    // masked softmax over rows
    if (tid < N) {
        int n = tid;
        float mx = -1e30f;
        for (int m = 0; m < N; m++) {
            bool ok = (abuf[n * 33 + m] > 0.5f) || (m == n);
            if (ok) mx = fmaxf(mx, Sbuf[n * 33 + m]);
        }
        float sum = 0.0f;
        for (int m = 0; m < N; m++) {
            bool ok = (abuf[n * 33 + m] > 0.5f) || (m == n);
            float e = ok ? expf(Sbuf[n * 33 + m] - mx) : 0.0f;
            Sbuf[n * 33 + m] = e;
            sum += e;
        }
        float inv = 1.0f / sum;
        for (int m = 0; m < N; m++) Sbuf[n * 33 + m] *= inv;
    }
    __syncthreads();

    // column sums of attention
    if (tid < N) {
        float c = 0.0f;
        for (int n = 0; n < N; n++) c += Sbuf[n * 33 + tid];
        csm[tid] = c;
    }
    __syncthreads();

    // out[d] = sum_m c[m] * h[m][d]
    float o = 0.0f;
    for (int m = 0; m < N; m++) o += csm[m] * hbuf[m * HP + tid];
    __syncthreads();   // buffers reusable after this
    return o;
}

__global__ __launch_bounds__(256) void graph_kernel(
    const int* __restrict__ idx_diag, const int* __restrict__ idx_proc,
    const int* __restrict__ idx_med,
    const float* __restrict__ adj_diag, const float* __restrict__ adj_proc,
    const float* __restrict__ adj_med,
    const float* __restrict__ w_dm, const float* __restrict__ w_pm,
    const float* __restrict__ rho,
    const float* __restrict__ HEd, const float* __restrict__ HEp,
    const float* __restrict__ HEm,
    const float* __restrict__ Temd, const float* __restrict__ Temp_,
    const float* __restrict__ Tedm, const float* __restrict__ Tepm,
    float* __restrict__ seq)
{
    __shared__ __align__(16) float hbuf[NDm * HP];
    __shared__ float Sbuf[NDm * 33];
    __shared__ float abuf[NDm * 33];
    __shared__ float wdm[NDm * NMm];
    __shared__ float wpm[NPm * NMm];
    __shared__ float csm[NDm];
    __shared__ float gd[NMm], gp[NMm], fd[NDm], fp[NPm];
    __shared__ float rsd[NDm], csd[NMm], rsp[NPm], csp[NMm];
    __shared__ int sidx_d[NDm], sidx_p[NPm], sidx_m[NMm];
    __shared__ float srho[6];

    int tid = threadIdx.x;
    int row = blockIdx.x;        // b*V + v
    int v = row % VV;

    if (tid < NDm) sidx_d[tid] = idx_diag[(long)row * NDm + tid];
    if (tid < NPm) sidx_p[tid] = idx_proc[(long)row * NPm + tid];
    if (tid < NMm) sidx_m[tid] = (v > 0) ? idx_med[(long)(row - 1) * NMm + tid] : 0;
    if (tid < 6) srho[tid] = rho[tid];
    __syncthreads();

    float od_ = homo_phase(HEd, sidx_d, adj_diag + (long)row * NDm * NDm, NDm,
                           hbuf, Sbuf, abuf, csm, tid);
    float op_ = homo_phase(HEp, sidx_p, adj_proc + (long)row * NPm * NPm, NPm,
                           hbuf, Sbuf, abuf, csm, tid);
    float om_ = 0.0f, hd2 = 0.0f, hp2 = 0.0f, hm2 = 0.0f;

    if (v > 0) {
        om_ = homo_phase(HEm, sidx_m, adj_med + (long)row * NMm * NMm, NMm,
                         hbuf, Sbuf, abuf, csm, tid);

        for (int i = tid; i < NDm * NMm; i += 256) wdm[i] = w_dm[(long)row * NDm * NMm + i];
        for (int i = tid; i < NPm * NMm; i += 256) wpm[i] = w_pm[(long)row * NPm * NMm + i];
        __syncthreads();

        if (tid < NDm) {                      // row sums of w_dm
            float s = 0; for (int m = 0; m < NMm; m++) s += wdm[tid * NMm + m];
            rsd[tid] = s;
        }
        if (tid >= 32 && tid < 32 + NMm) {    // col sums of w_dm
            int m = tid - 32; float s = 0;
            for (int n = 0; n < NDm; n++) s += wdm[n * NMm + m];
            csd[m] = s;
        }
        if (tid >= 64 && tid < 64 + NPm) {    // row sums of w_pm
            int n = tid - 64; float s = 0;
            for (int m = 0; m < NMm; m++) s += wpm[n * NMm + m];
            rsp[n] = s;
        }
        if (tid >= 96 && tid < 96 + NMm) {    // col sums of w_pm
            int m = tid - 96; float s = 0;
            for (int n = 0; n < NPm; n++) s += wpm[n * NMm + m];
            csp[m] = s;
        }
        __syncthreads();

        if (tid < NMm) {                      // g_d[m]
            float s = 0;
            for (int n = 0; n < NDm; n++) s += wdm[n * NMm + tid] / (rsd[n] + 1e-8f);
            gd[tid] = s;
        }
        if (tid >= 32 && tid < 32 + NDm) {    // f_d[n]
            int n = tid - 32; float s = 0;
            for (int m = 0; m < NMm; m++) s += wdm[n * NMm + m] / (csd[m] + 1e-8f);
            fd[n] = s;
        }
        if (tid >= 64 && tid < 64 + NMm) {    // g_p[m]
            int m = tid - 64; float s = 0;
            for (int n = 0; n < NPm; n++) s += wpm[n * NMm + m] / (rsp[n] + 1e-8f);
            gp[m] = s;
        }
        if (tid >= 96 && tid < 96 + NPm) {    // f_p[n]
            int n = tid - 96; float s = 0;
            for (int m = 0; m < NMm; m++) s += wpm[n * NMm + m] / (csp[m] + 1e-8f);
            fp[n] = s;
        }
        __syncthreads();

        // hetero gathers (precomputed right-multiplied tables)
        for (int m = 0; m < NMm; m++) {
            long base = (long)sidx_m[m] * DD + tid;
            hd2 += gd[m] * Temd[base];
            hp2 += gp[m] * Temp_[base];
        }
        for (int n = 0; n < NDm; n++) hm2 += fd[n] * Tedm[(long)sidx_d[n] * DD + tid];
        for (int n = 0; n < NPm; n++) hm2 += fp[n] * Tepm[(long)sidx_p[n] * DD + tid];
    }

    long o = (long)row * DD + tid;
    seq[o]                   = srho[0] * od_ + srho[1] * hd2;
    seq[6291456L / 3 + o]    = srho[2] * op_ + srho[3] * hp2;   // + 8192*256
    seq[2 * 2097152L + o]    = srho[4] * om_ + srho[5] * hm2;
}

// ---------------- SGEMM (TN):  C[M,N] = A[M,K] @ B[N,K]^T + bias[N] ----------------
// BM=BN=128, BK=8, 256 threads, 8x8 per thread. M%128==0, N%128==0, K%8==0.
__global__ __launch_bounds__(256, 2) void sgemm_tn(
    const float* __restrict__ A, long Az,
    const float* __restrict__ Bm, long Bz,
    const float* __restrict__ bias, long biasz,
    float* __restrict__ C, long Cz,
    int M, int N, int K)
{
    A += (long)blockIdx.z * Az;
    Bm += (long)blockIdx.z * Bz;
    C += (long)blockIdx.z * Cz;
    const float* bi = bias + (long)blockIdx.z * biasz;

    __shared__ __align__(16) float As[8][128];
    __shared__ __align__(16) float Bs[8][128];

    int tid = threadIdx.x;
    int tx = tid % 16, ty = tid / 16;
    int m0 = blockIdx.y * 128, n0 = blockIdx.x * 128;
    int lr = tid >> 1;             // 0..127
    int lk = (tid & 1) * 4;        // 0 or 4

    float acc[8][8];
#pragma unroll
    for (int i = 0; i < 8; i++)
#pragma unroll
        for (int j = 0; j < 8; j++) acc[i][j] = 0.0f;

    const float* Aptr = &A[(long)(m0 + lr) * K + lk];
    const float* Bptr = &Bm[(long)(n0 + lr) * K + lk];

    for (int k0 = 0; k0 < K; k0 += 8) {
        float4 a4 = *(const float4*)(Aptr + k0);
        float4 b4 = *(const float4*)(Bptr + k0);
        As[lk + 0][lr] = a4.x; As[lk + 1][lr] = a4.y;
        As[lk + 2][lr] = a4.z; As[lk + 3][lr] = a4.w;
        Bs[lk + 0][lr] = b4.x; Bs[lk + 1][lr] = b4.y;
        Bs[lk + 2][lr] = b4.z; Bs[lk + 3][lr] = b4.w;
        __syncthreads();
#pragma unroll
        for (int kk = 0; kk < 8; kk++) {
            float4 a0 = *(const float4*)&As[kk][ty * 8];
            float4 a1 = *(const float4*)&As[kk][ty * 8 + 4];
            float4 b0 = *(const float4*)&Bs[kk][tx * 8];
            float4 b1 = *(const float4*)&Bs[kk][tx * 8 + 4];
            float ar[8] = {a0.x,a0.y,a0.z,a0.w,a1.x,a1.y,a1.z,a1.w};
            float br[8] = {b0.x,b0.y,b0.z,b0.w,b1.x,b1.y,b1.z,b1.w};
#pragma unroll
            for (int i = 0; i < 8; i++)
#pragma unroll
                for (int j = 0; j < 8; j++) acc[i][j] += ar[i] * br[j];
        }
        __syncthreads();
    }

    float bj[8];
#pragma unroll
    for (int j = 0; j < 8; j++) bj[j] = bi[n0 + tx * 8 + j];
#pragma unroll
    for (int i = 0; i < 8; i++) {
        float* crow = &C[(long)(m0 + ty * 8 + i) * N + n0 + tx * 8];
        float4 v0 = make_float4(acc[i][0]+bj[0], acc[i][1]+bj[1], acc[i][2]+bj[2], acc[i][3]+bj[3]);
        float4 v1 = make_float4(acc[i][4]+bj[4], acc[i][5]+bj[5], acc[i][6]+bj[6], acc[i][7]+bj[7]);
        *(float4*)(crow) = v0;
        *(float4*)(crow + 4) = v1;
    }
}

// ---------------- misc small kernels ----------------
__global__ void zero_kernel(float* __restrict__ p, int n)
{
    int i = blockIdx.x * 256 + threadIdx.x;
    if (i < n) p[i] = 0.0f;
}

__global__ void gate_kernel(const float* __restrict__ gi, const float* __restrict__ gh,
                            float* __restrict__ h, int v)
{
    int idx = blockIdx.x * 256 + threadIdx.x;   // 3*1024*256
    int r = idx >> 18;            // / 262144
    int rem = idx & 262143;
    int b = rem >> 8;
    int d = rem & 255;
    const float* girow = gi + ((long)r * 8192 + (long)b * VV + v) * 768;
    const float* ghrow = gh + ((long)r * 1024 + b) * 768;
    float* hp = h + ((long)r * 1024 + b) * 256 + d;
    float hold = *hp;
    float rr = sigm(girow[d] + ghrow[d]);
    float z  = sigm(girow[256 + d] + ghrow[256 + d]);
    float n  = tanhf(girow[512 + d] + rr * ghrow[512 + d]);
    *hp = (1.0f - z) * n + z * hold;
}

__global__ void relu_assemble_kernel(const float* __restrict__ h, float* __restrict__ Hr)
{
    int idx = blockIdx.x * 256 + threadIdx.x;   // 3*1024*256
    int r = idx >> 18;
    int rem = idx & 262143;
    int b = rem >> 8;
    int d = rem & 255;
    Hr[(long)b * 768 + r * 256 + d] = fmaxf(h[idx], 0.0f);
}

__global__ void final1_kernel(const float* __restrict__ scorepad,
                              const float* __restrict__ ddi,
                              float* __restrict__ out, float* __restrict__ partials)
{
    __shared__ float p[VOC_M];
    __shared__ float red[256];
    int b = blockIdx.x, tid = threadIdx.x;
    if (tid < VOC_M) {
        float s = scorepad[(long)b * 256 + tid];
        out[(long)b * VOC_M + tid] = s;
        p[tid] = sigm(s);
    }
    __syncthreads();
    float part = 0.0f;
    if (tid < VOC_M) {
        float inner = 0.0f;
        for (int i = 0; i < VOC_M; i++) inner += p[i] * ddi[(long)i * VOC_M + tid];
        part = p[tid] * inner;
    }
    red[tid] = part;
    __syncthreads();
    for (int s = 128; s > 0; s >>= 1) {
        if (tid < s) red[tid] += red[tid + s];
        __syncthreads();
    }
    if (tid == 0) partials[b] = red[0];
}

__global__ void final2_kernel(const float* __restrict__ partials,
                              float* __restrict__ out, int out_size)
{
    __shared__ float red[256];
    int tid = threadIdx.x;
    float s = partials[tid] + partials[tid + 256] + partials[tid + 512] + partials[tid + 768];
    red[tid] = s;
    __syncthreads();
    for (int st = 128; st > 0; st >>= 1) {
        if (tid < st) red[tid] += red[tid + st];
        __syncthreads();
    }
    if (tid == 0 && out_size > BB * VOC_M) out[BB * VOC_M] = 0.0005f * red[0];
}

// ---------------- host launch ----------------
extern "C" void kernel_launch(void* const* d_in, const int* in_sizes, int n_in,
                              void* d_out, int out_size)
{
    const int* idx_diag = (const int*)d_in[0];
    const int* idx_proc = (const int*)d_in[1];
    const int* idx_med  = (const int*)d_in[2];
    const float* adj_diag = (const float*)d_in[3];
    const float* adj_proc = (const float*)d_in[4];
    const float* adj_med  = (const float*)d_in[5];
    const float* w_dm = (const float*)d_in[6];
    const float* w_pm = (const float*)d_in[7];
    const float* E_diag = (const float*)d_in[8];
    const float* E_proc = (const float*)d_in[9];
    const float* E_med  = (const float*)d_in[10];
    const float* W_homo = (const float*)d_in[11];
    const float* Wh_d  = (const float*)d_in[12];
    const float* Wh_p  = (const float*)d_in[13];
    const float* Wh_md = (const float*)d_in[14];
    const float* Wh_mp = (const float*)d_in[15];
    const float* rho   = (const float*)d_in[16];
    const float* gru_wih = (const float*)d_in[17];
    const float* gru_whh = (const float*)d_in[18];
    const float* gru_bih = (const float*)d_in[19];
    const float* gru_bhh = (const float*)d_in[20];
    const float* Wq = (const float*)d_in[21];
    const float* bq = (const float*)d_in[22];
    const float* ddi = (const float*)d_in[23];

    void* sp = nullptr;
    cudaGetSymbolAddress(&sp, g_scratch);
    float* S = (float*)sp;

    float* HEd   = S + OFF_HED;
    float* HEp   = S + OFF_HEP;
    float* HEm   = S + OFF_HEM;
    float* Temd  = S + OFF_TEMD;
    float* Temp_ = S + OFF_TEMP;
    float* Tedm  = S + OFF_TEDM;
    float* Tepm  = S + OFF_TEPM;
    float* seq   = S + OFF_SEQ;
    float* gi    = S + OFF_GI;
    float* h     = S + OFF_H;
    float* gh    = S + OFF_GH;
    float* Hr    = S + OFF_HR;
    float* Wq2p  = S + OFF_WQ2;
    float* bqp   = S + OFF_BQP;
    float* spad  = S + OFF_SP;
    float* part  = S + OFF_PART;

    // 1) precompute tables
    table_kernel<<<250, 256>>>(E_diag, W_homo,            HEd,  VOC_D);
    table_kernel<<<188, 256>>>(E_proc, W_homo + 65536,    HEp,  VOC_P);
    table_kernel<<<17,  256>>>(E_med,  W_homo + 131072,   HEm,  VOC_M);
    table_kernel<<<17,  256>>>(E_med,  Wh_d,              Temd, VOC_M);
    table_kernel<<<17,  256>>>(E_med,  Wh_p,              Temp_,VOC_M);
    table_kernel<<<250, 256>>>(E_diag, Wh_md,             Tedm, VOC_D);
    table_kernel<<<188, 256>>>(E_proc, Wh_mp,             Tepm, VOC_P);
    wq2_kernel<<<256, 256>>>(Wq, bq, Wq2p, bqp);

    // 2) fused per-visit graph kernel -> seq[3][8192][256]
    graph_kernel<<<BB * VV, 256>>>(idx_diag, idx_proc, idx_med,
                                   adj_diag, adj_proc, adj_med, w_dm, w_pm, rho,
                                   HEd, HEp, HEm, Temd, Temp_, Tedm, Tepm, seq);

    // 3) gi = seq @ wih^T + bih   (all visits, all 3 GRUs)
    sgemm_tn<<<dim3(6, 64, 3), 256>>>(seq, 8192L * 256, gru_wih, 768L * 256,
                                      gru_bih, 768, gi, 8192L * 768,
                                      8192, 768, 256);

    // 4) GRU recurrence
    zero_kernel<<<3072, 256>>>(h, 3 * 1024 * 256);
    for (int v = 0; v < VV; v++) {
        sgemm_tn<<<dim3(6, 8, 3), 256>>>(h, 1024L * 256, gru_whh, 768L * 256,
                                         gru_bhh, 768, gh, 1024L * 768,
                                         1024, 768, 256);
        gate_kernel<<<3072, 256>>>(gi, gh, h, v);
    }

    // 5) final score GEMM (Wq folded: repr duplication -> Wq2)
    relu_assemble_kernel<<<3072, 256>>>(h, Hr);
    sgemm_tn<<<dim3(2, 8, 1), 256>>>(Hr, 0, Wq2p, 0, bqp, 0, spad, 0,
                                     1024, 256, 768);

    // 6) outputs: score + ddi batch_neg
    final1_kernel<<<BB, 256>>>(spad, ddi, (float*)d_out, part);
    final2_kernel<<<1, 256>>>(part, (float*)d_out, out_size);
}

// round 2
// speedup vs baseline: 1.1995x; 1.1995x over previous
#include <cuda_runtime.h>
#include <cstdint>

#define BB 1024
#define VV 8
#define NDm 32
#define NPm 16
#define NMm 24
#define DD 256
#define VOC_D 2000
#define VOC_P 1500
#define VOC_M 131

// ---------------- scratch layout (floats) ----------------
#define OFF_HED   0L
#define OFF_HEP   512000L
#define OFF_HEM   896000L
#define OFF_TEMD  929536L
#define OFF_TEMP  963072L
#define OFF_TEDM  996608L
#define OFF_TEPM  1508608L
#define OFF_SEQ   1892608L        // [3][8192][256]
#define OFF_GI    8184064L        // [3][8192][768]
#define OFF_H     27058432L       // [3][1024][256]
#define OFF_GH    27844864L       // [3][1024][768]
#define OFF_HR    30204160L       // [1024][768]
#define OFF_WQ2   30990592L       // [256][768]
#define OFF_BQP   31187200L       // [256]
#define OFF_SP    31187456L       // [1024][256]
#define OFF_PART  31449600L       // [1024]
#define SCRATCH_TOTAL 31450624L

__device__ __align__(256) float g_scratch[SCRATCH_TOTAL];

__device__ __forceinline__ float dot4(float4 a, float4 b) {
    return a.x*b.x + a.y*b.y + a.z*b.z + a.w*b.w;
}
__device__ __forceinline__ float sigm(float x) { return 1.0f / (1.0f + expf(-x)); }

// ---------------- Fused table precompute: 7 jobs + Wq2 fold, one launch ----------
// Table jobs: dst[r,:] = E[r,:] @ W (DD x DD), 16 rows per block, 256 threads.
// Block ranges: [0,125) HEd | [125,219) HEp | [219,228) HEm | [228,237) Temd
//               [237,246) Temp | [246,371) Tedm | [371,465) Tepm | [465,721) wq2
__global__ __launch_bounds__(256) void tables_kernel(
    const float* __restrict__ E_diag, const float* __restrict__ E_proc,
    const float* __restrict__ E_med,  const float* __restrict__ W_homo,
    const float* __restrict__ Wh_d,   const float* __restrict__ Wh_p,
    const float* __restrict__ Wh_md,  const float* __restrict__ Wh_mp,
    const float* __restrict__ Wq,     const float* __restrict__ bq,
    float* __restrict__ HEd, float* __restrict__ HEp, float* __restrict__ HEm,
    float* __restrict__ Temd, float* __restrict__ Temp_,
    float* __restrict__ Tedm, float* __restrict__ Tepm,
    float* __restrict__ Wq2p, float* __restrict__ bqp)
{
    int blk = blockIdx.x;
    int tid = threadIdx.x;

    if (blk >= 465) {                         // ---- Wq2 fold ----
        int j = blk - 465;                    // 0..255
        for (int c = tid; c < 768; c += 256) {
            float v = 0.0f;
            if (j < VOC_M) v = Wq[(long)j * 1536 + c] + Wq[(long)j * 1536 + 768 + c];
            Wq2p[(long)j * 768 + c] = v;
        }
        if (tid == 0) bqp[j] = (j < VOC_M) ? bq[j] : 0.0f;
        return;
    }

    const float* E; const float* W; float* dst; int rows; int r0;
    if (blk < 125)      { E = E_diag; W = W_homo;          dst = HEd;   rows = VOC_D; r0 = blk * 16; }
    else if (blk < 219) { E = E_proc; W = W_homo + 65536;  dst = HEp;   rows = VOC_P; r0 = (blk-125)*16; }
    else if (blk < 228) { E = E_med;  W = W_homo + 131072; dst = HEm;   rows = VOC_M; r0 = (blk-219)*16; }
    else if (blk < 237) { E = E_med;  W = Wh_d;            dst = Temd;  rows = VOC_M; r0 = (blk-228)*16; }
    else if (blk < 246) { E = E_med;  W = Wh_p;            dst = Temp_; rows = VOC_M; r0 = (blk-237)*16; }
    else if (blk < 371) { E = E_diag; W = Wh_md;           dst = Tedm;  rows = VOC_D; r0 = (blk-246)*16; }
    else                { E = E_proc; W = Wh_mp;           dst = Tepm;  rows = VOC_P; r0 = (blk-371)*16; }

    __shared__ __align__(16) float e[16][DD];
    for (int i = tid; i < 16 * (DD / 4); i += 256) {
        int rr = i >> 6;              // / (DD/4)
        int cc = (i & 63) << 2;
        float4 v = make_float4(0.f, 0.f, 0.f, 0.f);
        if (r0 + rr < rows) v = *(const float4*)&E[(long)(r0 + rr) * DD + cc];
        *(float4*)&e[rr][cc] = v;
    }
    __syncthreads();

    float acc[16];
#pragma unroll
    for (int i = 0; i < 16; i++) acc[i] = 0.0f;
#pragma unroll 4
    for (int k = 0; k < DD; k++) {
        float w = W[(long)k * DD + tid];
#pragma unroll
        for (int i = 0; i < 16; i++) acc[i] += e[i][k] * w;
    }
#pragma unroll
    for (int i = 0; i < 16; i++)
        if (r0 + i < rows) dst[(long)(r0 + i) * DD + tid] = acc[i];
}

// ---------------- per-(b,v) fused graph kernel ----------------
#define HP 260   // padded row stride for h buffer

__device__ float homo_phase(const float* __restrict__ table, const int* sidx,
                            const float* __restrict__ adjg, int N,
                            float* hbuf, float* Sbuf, float* abuf, float* csm, int tid)
{
    for (int r = 0; r < N; r++)
        hbuf[r * HP + tid] = table[(long)sidx[r] * DD + tid];
    for (int i = tid; i < N * N; i += 256)
        abuf[(i / N) * 33 + (i % N)] = adjg[i];
    __syncthreads();

    int half = N >> 1;
    if (tid < half * half) {
        int tn = tid / half, tm = tid % half;
        const float* A0 = &hbuf[(2 * tn) * HP];
        const float* A1 = A0 + HP;
        const float* B0 = &hbuf[(2 * tm) * HP];
        const float* B1 = B0 + HP;
        float s00 = 0, s01 = 0, s10 = 0, s11 = 0;
#pragma unroll 4
        for (int k = 0; k < DD; k += 4) {
            float4 a0 = *(const float4*)(A0 + k);
            float4 a1 = *(const float4*)(A1 + k);
            float4 b0 = *(const float4*)(B0 + k);
            float4 b1 = *(const float4*)(B1 + k);
            s00 += dot4(a0, b0); s01 += dot4(a0, b1);
            s10 += dot4(a1, b0); s11 += dot4(a1, b1);
        }
        Sbuf[(2 * tn) * 33 + 2 * tm]         = s00 * 0.0625f;
        Sbuf[(2 * tn) * 33 + 2 * tm + 1]     = s01 * 0.0625f;
        Sbuf[(2 * tn + 1) * 33 + 2 * tm]     = s10 * 0.0625f;
        Sbuf[(2 * tn + 1) * 33 + 2 * tm + 1] = s11 * 0.0625f;
    }
    __syncthreads();

    if (tid < N) {
        int n = tid;
        float mx = -1e30f;
        for (int m = 0; m < N; m++) {
            bool ok = (abuf[n * 33 + m] > 0.5f) || (m == n);
            if (ok) mx = fmaxf(mx, Sbuf[n * 33 + m]);
        }
        float sum = 0.0f;
        for (int m = 0; m < N; m++) {
            bool ok = (abuf[n * 33 + m] > 0.5f) || (m == n);
            float e = ok ? expf(Sbuf[n * 33 + m] - mx) : 0.0f;
            Sbuf[n * 33 + m] = e;
            sum += e;
        }
        float inv = 1.0f / sum;
        for (int m = 0; m < N; m++) Sbuf[n * 33 + m] *= inv;
    }
    __syncthreads();

    if (tid < N) {
        float c = 0.0f;
        for (int n = 0; n < N; n++) c += Sbuf[n * 33 + tid];
        csm[tid] = c;
    }
    __syncthreads();

    float o = 0.0f;
    for (int m = 0; m < N; m++) o += csm[m] * hbuf[m * HP + tid];
    __syncthreads();
    return o;
}

__global__ __launch_bounds__(256) void graph_kernel(
    const int* __restrict__ idx_diag, const int* __restrict__ idx_proc,
    const int* __restrict__ idx_med,
    const float* __restrict__ adj_diag, const float* __restrict__ adj_proc,
    const float* __restrict__ adj_med,
    const float* __restrict__ w_dm, const float* __restrict__ w_pm,
    const float* __restrict__ rho,
    const float* __restrict__ HEd, const float* __restrict__ HEp,
    const float* __restrict__ HEm,
    const float* __restrict__ Temd, const float* __restrict__ Temp_,
    const float* __restrict__ Tedm, const float* __restrict__ Tepm,
    float* __restrict__ seq)
{
    __shared__ __align__(16) float hbuf[NDm * HP];
    __shared__ float Sbuf[NDm * 33];
    __shared__ float abuf[NDm * 33];
    __shared__ float wdm[NDm * NMm];
    __shared__ float wpm[NPm * NMm];
    __shared__ float csm[NDm];
    __shared__ float gd[NMm], gp[NMm], fd[NDm], fp[NPm];
    __shared__ float rsd[NDm], csd[NMm], rsp[NPm], csp[NMm];
    __shared__ int sidx_d[NDm], sidx_p[NPm], sidx_m[NMm];
    __shared__ float srho[6];

    int tid = threadIdx.x;
    int row = blockIdx.x;
    int v = row % VV;

    if (tid < NDm) sidx_d[tid] = idx_diag[(long)row * NDm + tid];
    if (tid < NPm) sidx_p[tid] = idx_proc[(long)row * NPm + tid];
    if (tid < NMm) sidx_m[tid] = (v > 0) ? idx_med[(long)(row - 1) * NMm + tid] : 0;
    if (tid < 6) srho[tid] = rho[tid];
    __syncthreads();

    float od_ = homo_phase(HEd, sidx_d, adj_diag + (long)row * NDm * NDm, NDm,
                           hbuf, Sbuf, abuf, csm, tid);
    float op_ = homo_phase(HEp, sidx_p, adj_proc + (long)row * NPm * NPm, NPm,
                           hbuf, Sbuf, abuf, csm, tid);
    float om_ = 0.0f, hd2 = 0.0f, hp2 = 0.0f, hm2 = 0.0f;

    if (v > 0) {
        om_ = homo_phase(HEm, sidx_m, adj_med + (long)row * NMm * NMm, NMm,
                         hbuf, Sbuf, abuf, csm, tid);

        for (int i = tid; i < NDm * NMm; i += 256) wdm[i] = w_dm[(long)row * NDm * NMm + i];
        for (int i = tid; i < NPm * NMm; i += 256) wpm[i] = w_pm[(long)row * NPm * NMm + i];
        __syncthreads();

        if (tid < NDm) {
            float s = 0; for (int m = 0; m < NMm; m++) s += wdm[tid * NMm + m];
            rsd[tid] = s;
        }
        if (tid >= 32 && tid < 32 + NMm) {
            int m = tid - 32; float s = 0;
            for (int n = 0; n < NDm; n++) s += wdm[n * NMm + m];
            csd[m] = s;
        }
        if (tid >= 64 && tid < 64 + NPm) {
            int n = tid - 64; float s = 0;
            for (int m = 0; m < NMm; m++) s += wpm[n * NMm + m];
            rsp[n] = s;
        }
        if (tid >= 96 && tid < 96 + NMm) {
            int m = tid - 96; float s = 0;
            for (int n = 0; n < NPm; n++) s += wpm[n * NMm + m];
            csp[m] = s;
        }
        __syncthreads();

        if (tid < NMm) {
            float s = 0;
            for (int n = 0; n < NDm; n++) s += wdm[n * NMm + tid] / (rsd[n] + 1e-8f);
            gd[tid] = s;
        }
        if (tid >= 32 && tid < 32 + NDm) {
            int n = tid - 32; float s = 0;
            for (int m = 0; m < NMm; m++) s += wdm[n * NMm + m] / (csd[m] + 1e-8f);
            fd[n] = s;
        }
        if (tid >= 64 && tid < 64 + NMm) {
            int m = tid - 64; float s = 0;
            for (int n = 0; n < NPm; n++) s += wpm[n * NMm + m] / (rsp[n] + 1e-8f);
            gp[m] = s;
        }
        if (tid >= 96 && tid < 96 + NPm) {
            int n = tid - 96; float s = 0;
            for (int m = 0; m < NMm; m++) s += wpm[n * NMm + m] / (csp[m] + 1e-8f);
            fp[n] = s;
        }
        __syncthreads();

        for (int m = 0; m < NMm; m++) {
            long base = (long)sidx_m[m] * DD + tid;
            hd2 += gd[m] * Temd[base];
            hp2 += gp[m] * Temp_[base];
        }
        for (int n = 0; n < NDm; n++) hm2 += fd[n] * Tedm[(long)sidx_d[n] * DD + tid];
        for (int n = 0; n < NPm; n++) hm2 += fp[n] * Tepm[(long)sidx_p[n] * DD + tid];
    }

    long o = (long)row * DD + tid;
    seq[o]                = srho[0] * od_ + srho[1] * hd2;
    seq[2097152L + o]     = srho[2] * op_ + srho[3] * hp2;
    seq[2L * 2097152L + o] = srho[4] * om_ + srho[5] * hm2;
}

// ---------------- SGEMM (TN), double-buffered:  C = A @ B^T + bias ----------------
// BM=BN=128, BK=16, 256 threads, 8x8 per thread. M%128==0, N%128==0, K%16==0.
__global__ __launch_bounds__(256, 2) void sgemm_tn(
    const float* __restrict__ A, long Az,
    const float* __restrict__ Bm, long Bz,
    const float* __restrict__ bias, long biasz,
    float* __restrict__ C, long Cz,
    int M, int N, int K)
{
    A += (long)blockIdx.z * Az;
    Bm += (long)blockIdx.z * Bz;
    C += (long)blockIdx.z * Cz;
    const float* bi = bias + (long)blockIdx.z * biasz;

    __shared__ __align__(16) float As[2][16][128];
    __shared__ __align__(16) float Bs[2][16][128];

    int tid = threadIdx.x;
    int tx = tid % 16, ty = tid / 16;
    int m0 = blockIdx.y * 128, n0 = blockIdx.x * 128;
    int lr = tid >> 1;             // 0..127
    int lk = (tid & 1) * 8;        // 0 or 8

    const float* Aptr = &A[(long)(m0 + lr) * K + lk];
    const float* Bptr = &Bm[(long)(n0 + lr) * K + lk];

    float acc[8][8];
#pragma unroll
    for (int i = 0; i < 8; i++)
#pragma unroll
        for (int j = 0; j < 8; j++) acc[i][j] = 0.0f;

    // prologue: tile 0 into buffer 0
    {
        float4 a0 = *(const float4*)(Aptr);
        float4 a1 = *(const float4*)(Aptr + 4);
        float4 b0 = *(const float4*)(Bptr);
        float4 b1 = *(const float4*)(Bptr + 4);
        As[0][lk + 0][lr] = a0.x; As[0][lk + 1][lr] = a0.y;
        As[0][lk + 2][lr] = a0.z; As[0][lk + 3][lr] = a0.w;
        As[0][lk + 4][lr] = a1.x; As[0][lk + 5][lr] = a1.y;
        As[0][lk + 6][lr] = a1.z; As[0][lk + 7][lr] = a1.w;
        Bs[0][lk + 0][lr] = b0.x; Bs[0][lk + 1][lr] = b0.y;
        Bs[0][lk + 2][lr] = b0.z; Bs[0][lk + 3][lr] = b0.w;
        Bs[0][lk + 4][lr] = b1.x; Bs[0][lk + 5][lr] = b1.y;
        Bs[0][lk + 6][lr] = b1.z; Bs[0][lk + 7][lr] = b1.w;
    }
    __syncthreads();

    int T = K >> 4;
    for (int t = 0; t < T; t++) {
        int cur = t & 1;
        float4 na0, na1, nb0, nb1;
        if (t + 1 < T) {
            const float* Ap = Aptr + (t + 1) * 16;
            const float* Bp = Bptr + (t + 1) * 16;
            na0 = *(const float4*)(Ap);
            na1 = *(const float4*)(Ap + 4);
            nb0 = *(const float4*)(Bp);
            nb1 = *(const float4*)(Bp + 4);
        }
#pragma unroll
        for (int kk = 0; kk < 16; kk++) {
            float4 x0 = *(const float4*)&As[cur][kk][ty * 8];
            float4 x1 = *(const float4*)&As[cur][kk][ty * 8 + 4];
            float4 y0 = *(const float4*)&Bs[cur][kk][tx * 8];
            float4 y1 = *(const float4*)&Bs[cur][kk][tx * 8 + 4];
            float ar[8] = {x0.x,x0.y,x0.z,x0.w,x1.x,x1.y,x1.z,x1.w};
            float br[8] = {y0.x,y0.y,y0.z,y0.w,y1.x,y1.y,y1.z,y1.w};
#pragma unroll
            for (int i = 0; i < 8; i++)
#pragma unroll
                for (int j = 0; j < 8; j++) acc[i][j] += ar[i] * br[j];
        }
        if (t + 1 < T) {
            int nb = cur ^ 1;
            As[nb][lk + 0][lr] = na0.x; As[nb][lk + 1][lr] = na0.y;
            As[nb][lk + 2][lr] = na0.z; As[nb][lk + 3][lr] = na0.w;
            As[nb][lk + 4][lr] = na1.x; As[nb][lk + 5][lr] = na1.y;
            As[nb][lk + 6][lr] = na1.z; As[nb][lk + 7][lr] = na1.w;
            Bs[nb][lk + 0][lr] = nb0.x; Bs[nb][lk + 1][lr] = nb0.y;
            Bs[nb][lk + 2][lr] = nb0.z; Bs[nb][lk + 3][lr] = nb0.w;
            Bs[nb][lk + 4][lr] = nb1.x; Bs[nb][lk + 5][lr] = nb1.y;
            Bs[nb][lk + 6][lr] = nb1.z; Bs[nb][lk + 7][lr] = nb1.w;
            __syncthreads();
        }
    }

    float bj[8];
#pragma unroll
    for (int j = 0; j < 8; j++) bj[j] = bi[n0 + tx * 8 + j];
#pragma unroll
    for (int i = 0; i < 8; i++) {
        float* crow = &C[(long)(m0 + ty * 8 + i) * N + n0 + tx * 8];
        float4 v0 = make_float4(acc[i][0]+bj[0], acc[i][1]+bj[1], acc[i][2]+bj[2], acc[i][3]+bj[3]);
        float4 v1 = make_float4(acc[i][4]+bj[4], acc[i][5]+bj[5], acc[i][6]+bj[6], acc[i][7]+bj[7]);
        *(float4*)(crow) = v0;
        *(float4*)(crow + 4) = v1;
    }
}

// ---------------- GRU gate kernels ----------------
__global__ void gate0_kernel(const float* __restrict__ gi, const float* __restrict__ bhh,
                             float* __restrict__ h)
{
    int idx = blockIdx.x * 256 + threadIdx.x;   // 3*1024*256
    int r = idx >> 18;
    int rem = idx & 262143;
    int b = rem >> 8;
    int d = rem & 255;
    const float* girow = gi + ((long)r * 8192 + (long)b * VV) * 768;
    const float* bh = bhh + (long)r * 768;
    float z  = sigm(girow[256 + d] + bh[256 + d]);
    float rr = sigm(girow[d] + bh[d]);
    float n  = tanhf(girow[512 + d] + rr * bh[512 + d]);
    h[idx] = (1.0f - z) * n;
}

__global__ void gate_kernel(const float* __restrict__ gi, const float* __restrict__ gh,
                            float* __restrict__ h, int v)
{
    int idx = blockIdx.x * 256 + threadIdx.x;
    int r = idx >> 18;
    int rem = idx & 262143;
    int b = rem >> 8;
    int d = rem & 255;
    const float* girow = gi + ((long)r * 8192 + (long)b * VV + v) * 768;
    const float* ghrow = gh + ((long)r * 1024 + b) * 768;
    float hold = h[idx];
    float rr = sigm(girow[d] + ghrow[d]);
    float z  = sigm(girow[256 + d] + ghrow[256 + d]);
    float n  = tanhf(girow[512 + d] + rr * ghrow[512 + d]);
    h[idx] = (1.0f - z) * n + z * hold;
}

__global__ void relu_assemble_kernel(const float* __restrict__ h, float* __restrict__ Hr)
{
    int idx = blockIdx.x * 256 + threadIdx.x;
    int r = idx >> 18;
    int rem = idx & 262143;
    int b = rem >> 8;
    int d = rem & 255;
    Hr[(long)b * 768 + r * 256 + d] = fmaxf(h[idx], 0.0f);
}

__global__ void final1_kernel(const float* __restrict__ scorepad,
                              const float* __restrict__ ddi,
                              float* __restrict__ out, float* __restrict__ partials)
{
    __shared__ float p[VOC_M];
    __shared__ float red[256];
    int b = blockIdx.x, tid = threadIdx.x;
    if (tid < VOC_M) {
        float s = scorepad[(long)b * 256 + tid];
        out[(long)b * VOC_M + tid] = s;
        p[tid] = sigm(s);
    }
    __syncthreads();
    float part = 0.0f;
    if (tid < VOC_M) {
        float inner = 0.0f;
        for (int i = 0; i < VOC_M; i++) inner += p[i] * ddi[(long)i * VOC_M + tid];
        part = p[tid] * inner;
    }
    red[tid] = part;
    __syncthreads();
    for (int s = 128; s > 0; s >>= 1) {
        if (tid < s) red[tid] += red[tid + s];
        __syncthreads();
    }
    if (tid == 0) partials[b] = red[0];
}

__global__ void final2_kernel(const float* __restrict__ partials,
                              float* __restrict__ out, int out_size)
{
    __shared__ float red[256];
    int tid = threadIdx.x;
    float s = partials[tid] + partials[tid + 256] + partials[tid + 512] + partials[tid + 768];
    red[tid] = s;
    __syncthreads();
    for (int st = 128; st > 0; st >>= 1) {
        if (tid < st) red[tid] += red[tid + st];
        __syncthreads();
    }
    if (tid == 0 && out_size > BB * VOC_M) out[BB * VOC_M] = 0.0005f * red[0];
}

// ---------------- host launch ----------------
extern "C" void kernel_launch(void* const* d_in, const int* in_sizes, int n_in,
                              void* d_out, int out_size)
{
    const int* idx_diag = (const int*)d_in[0];
    const int* idx_proc = (const int*)d_in[1];
    const int* idx_med  = (const int*)d_in[2];
    const float* adj_diag = (const float*)d_in[3];
    const float* adj_proc = (const float*)d_in[4];
    const float* adj_med  = (const float*)d_in[5];
    const float* w_dm = (const float*)d_in[6];
    const float* w_pm = (const float*)d_in[7];
    const float* E_diag = (const float*)d_in[8];
    const float* E_proc = (const float*)d_in[9];
    const float* E_med  = (const float*)d_in[10];
    const float* W_homo = (const float*)d_in[11];
    const float* Wh_d  = (const float*)d_in[12];
    const float* Wh_p  = (const float*)d_in[13];
    const float* Wh_md = (const float*)d_in[14];
    const float* Wh_mp = (const float*)d_in[15];
    const float* rho   = (const float*)d_in[16];
    const float* gru_wih = (const float*)d_in[17];
    const float* gru_whh = (const float*)d_in[18];
    const float* gru_bih = (const float*)d_in[19];
    const float* gru_bhh = (const float*)d_in[20];
    const float* Wq = (const float*)d_in[21];
    const float* bq = (const float*)d_in[22];
    const float* ddi = (const float*)d_in[23];

    void* sp = nullptr;
    cudaGetSymbolAddress(&sp, g_scratch);
    float* S = (float*)sp;

    float* HEd   = S + OFF_HED;
    float* HEp   = S + OFF_HEP;
    float* HEm   = S + OFF_HEM;
    float* Temd  = S + OFF_TEMD;
    float* Temp_ = S + OFF_TEMP;
    float* Tedm  = S + OFF_TEDM;
    float* Tepm  = S + OFF_TEPM;
    float* seq   = S + OFF_SEQ;
    float* gi    = S + OFF_GI;
    float* h     = S + OFF_H;
    float* gh    = S + OFF_GH;
    float* Hr    = S + OFF_HR;
    float* Wq2p  = S + OFF_WQ2;
    float* bqp   = S + OFF_BQP;
    float* spad  = S + OFF_SP;
    float* part  = S + OFF_PART;

    // 1) all table precompute in one launch
    tables_kernel<<<721, 256>>>(E_diag, E_proc, E_med, W_homo, Wh_d, Wh_p, Wh_md, Wh_mp,
                                Wq, bq, HEd, HEp, HEm, Temd, Temp_, Tedm, Tepm, Wq2p, bqp);

    // 2) fused per-visit graph kernel -> seq[3][8192][256]
    graph_kernel<<<BB * VV, 256>>>(idx_diag, idx_proc, idx_med,
                                   adj_diag, adj_proc, adj_med, w_dm, w_pm, rho,
                                   HEd, HEp, HEm, Temd, Temp_, Tedm, Tepm, seq);

    // 3) gi = seq @ wih^T + bih
    sgemm_tn<<<dim3(6, 64, 3), 256>>>(seq, 8192L * 256, gru_wih, 768L * 256,
                                      gru_bih, 768, gi, 8192L * 768,
                                      8192, 768, 256);

    // 4) GRU recurrence (step 0 specialized: h=0 -> gh = bhh)
    gate0_kernel<<<3072, 256>>>(gi, gru_bhh, h);
    for (int v = 1; v < VV; v++) {
        sgemm_tn<<<dim3(6, 8, 3), 256>>>(h, 1024L * 256, gru_whh, 768L * 256,
                                         gru_bhh, 768, gh, 1024L * 768,
                                         1024, 768, 256);
        gate_kernel<<<3072, 256>>>(gi, gh, h, v);
    }

    // 5) final score GEMM
    relu_assemble_kernel<<<3072, 256>>>(h, Hr);
    sgemm_tn<<<dim3(2, 8, 1), 256>>>(Hr, 0, Wq2p, 0, bqp, 0, spad, 0,
                                     1024, 256, 768);

    // 6) outputs
    final1_kernel<<<BB, 256>>>(spad, ddi, (float*)d_out, part);
    final2_kernel<<<1, 256>>>(part, (float*)d_out, out_size);
}

// round 3
// speedup vs baseline: 1.4447x; 1.2044x over previous
#include <cuda_runtime.h>
#include <cstdint>

#define BB 1024
#define VV 8
#define NDm 32
#define NPm 16
#define NMm 24
#define DD 256
#define VOC_D 2000
#define VOC_P 1500
#define VOC_M 131

// ---------------- scratch layout (floats) ----------------
#define OFF_HED   0L
#define OFF_HEP   512000L
#define OFF_HEM   896000L
#define OFF_TEMD  929536L
#define OFF_TEMP  963072L
#define OFF_TEDM  996608L
#define OFF_TEPM  1508608L
#define OFF_SEQ   1892608L        // [3][8192][256]
#define OFF_GI    8184064L        // [3][8192][768]
#define OFF_H     27058432L       // [3][1024][256]
#define OFF_GH    27844864L       // [3][1024][768]
#define OFF_HR    30204160L       // [1024][768]
#define OFF_WQ2   30990592L       // [256][768]
#define OFF_BQP   31187200L       // [256]
#define OFF_SP    31187456L       // [1024][256]
#define OFF_PART  31449600L       // [1024]
#define SCRATCH_TOTAL 31450624L

__device__ __align__(256) float g_scratch[SCRATCH_TOTAL];

__device__ __forceinline__ float dot4(float4 a, float4 b) {
    return a.x*b.x + a.y*b.y + a.z*b.z + a.w*b.w;
}
__device__ __forceinline__ float sigm(float x) { return 1.0f / (1.0f + expf(-x)); }
__device__ __forceinline__ uint32_t f2tf32(float x) {
    uint32_t r;
    asm("cvt.rna.tf32.f32 %0, %1;" : "=r"(r) : "f"(x));
    return r;
}

// ---------------- Fused table precompute: 7 jobs + Wq2 fold ----------------
__global__ __launch_bounds__(256) void tables_kernel(
    const float* __restrict__ E_diag, const float* __restrict__ E_proc,
    const float* __restrict__ E_med,  const float* __restrict__ W_homo,
    const float* __restrict__ Wh_d,   const float* __restrict__ Wh_p,
    const float* __restrict__ Wh_md,  const float* __restrict__ Wh_mp,
    const float* __restrict__ Wq,     const float* __restrict__ bq,
    float* __restrict__ HEd, float* __restrict__ HEp, float* __restrict__ HEm,
    float* __restrict__ Temd, float* __restrict__ Temp_,
    float* __restrict__ Tedm, float* __restrict__ Tepm,
    float* __restrict__ Wq2p, float* __restrict__ bqp)
{
    int blk = blockIdx.x;
    int tid = threadIdx.x;

    if (blk >= 465) {                         // ---- Wq2 fold ----
        int j = blk - 465;
        for (int c = tid; c < 768; c += 256) {
            float v = 0.0f;
            if (j < VOC_M) v = Wq[(long)j * 1536 + c] + Wq[(long)j * 1536 + 768 + c];
            Wq2p[(long)j * 768 + c] = v;
        }
        if (tid == 0) bqp[j] = (j < VOC_M) ? bq[j] : 0.0f;
        return;
    }

    const float* E; const float* W; float* dst; int rows; int r0;
    if (blk < 125)      { E = E_diag; W = W_homo;          dst = HEd;   rows = VOC_D; r0 = blk * 16; }
    else if (blk < 219) { E = E_proc; W = W_homo + 65536;  dst = HEp;   rows = VOC_P; r0 = (blk-125)*16; }
    else if (blk < 228) { E = E_med;  W = W_homo + 131072; dst = HEm;   rows = VOC_M; r0 = (blk-219)*16; }
    else if (blk < 237) { E = E_med;  W = Wh_d;            dst = Temd;  rows = VOC_M; r0 = (blk-228)*16; }
    else if (blk < 246) { E = E_med;  W = Wh_p;            dst = Temp_; rows = VOC_M; r0 = (blk-237)*16; }
    else if (blk < 371) { E = E_diag; W = Wh_md;           dst = Tedm;  rows = VOC_D; r0 = (blk-246)*16; }
    else                { E = E_proc; W = Wh_mp;           dst = Tepm;  rows = VOC_P; r0 = (blk-371)*16; }

    __shared__ __align__(16) float e[16][DD];
    for (int i = tid; i < 16 * (DD / 4); i += 256) {
        int rr = i >> 6;
        int cc = (i & 63) << 2;
        float4 v = make_float4(0.f, 0.f, 0.f, 0.f);
        if (r0 + rr < rows) v = *(const float4*)&E[(long)(r0 + rr) * DD + cc];
        *(float4*)&e[rr][cc] = v;
    }
    __syncthreads();

    float acc[16];
#pragma unroll
    for (int i = 0; i < 16; i++) acc[i] = 0.0f;
#pragma unroll 4
    for (int k = 0; k < DD; k++) {
        float w = W[(long)k * DD + tid];
#pragma unroll
        for (int i = 0; i < 16; i++) acc[i] += e[i][k] * w;
    }
#pragma unroll
    for (int i = 0; i < 16; i++)
        if (r0 + i < rows) dst[(long)(r0 + i) * DD + tid] = acc[i];
}

// ---------------- per-(b,v) fused graph kernel ----------------
#define HP 260

__device__ float homo_phase(const float* __restrict__ table, const int* sidx,
                            const float* __restrict__ adjg, int N,
                            float* hbuf, float* Sbuf, float* abuf, float* csm, int tid)
{
    for (int r = 0; r < N; r++)
        hbuf[r * HP + tid] = table[(long)sidx[r] * DD + tid];
    for (int i = tid; i < N * N; i += 256)
        abuf[(i / N) * 33 + (i % N)] = adjg[i];
    __syncthreads();

    int half = N >> 1;
    if (tid < half * half) {
        int tn = tid / half, tm = tid % half;
        const float* A0 = &hbuf[(2 * tn) * HP];
        const float* A1 = A0 + HP;
        const float* B0 = &hbuf[(2 * tm) * HP];
        const float* B1 = B0 + HP;
        float s00 = 0, s01 = 0, s10 = 0, s11 = 0;
#pragma unroll 4
        for (int k = 0; k < DD; k += 4) {
            float4 a0 = *(const float4*)(A0 + k);
            float4 a1 = *(const float4*)(A1 + k);
            float4 b0 = *(const float4*)(B0 + k);
            float4 b1 = *(const float4*)(B1 + k);
            s00 += dot4(a0, b0); s01 += dot4(a0, b1);
            s10 += dot4(a1, b0); s11 += dot4(a1, b1);
        }
        Sbuf[(2 * tn) * 33 + 2 * tm]         = s00 * 0.0625f;
        Sbuf[(2 * tn) * 33 + 2 * tm + 1]     = s01 * 0.0625f;
        Sbuf[(2 * tn + 1) * 33 + 2 * tm]     = s10 * 0.0625f;
        Sbuf[(2 * tn + 1) * 33 + 2 * tm + 1] = s11 * 0.0625f;
    }
    __syncthreads();

    if (tid < N) {
        int n = tid;
        float mx = -1e30f;
        for (int m = 0; m < N; m++) {
            bool ok = (abuf[n * 33 + m] > 0.5f) || (m == n);
            if (ok) mx = fmaxf(mx, Sbuf[n * 33 + m]);
        }
        float sum = 0.0f;
        for (int m = 0; m < N; m++) {
            bool ok = (abuf[n * 33 + m] > 0.5f) || (m == n);
            float e = ok ? expf(Sbuf[n * 33 + m] - mx) : 0.0f;
            Sbuf[n * 33 + m] = e;
            sum += e;
        }
        float inv = 1.0f / sum;
        for (int m = 0; m < N; m++) Sbuf[n * 33 + m] *= inv;
    }
    __syncthreads();

    if (tid < N) {
        float c = 0.0f;
        for (int n = 0; n < N; n++) c += Sbuf[n * 33 + tid];
        csm[tid] = c;
    }
    __syncthreads();

    float o = 0.0f;
    for (int m = 0; m < N; m++) o += csm[m] * hbuf[m * HP + tid];
    __syncthreads();
    return o;
}

__global__ __launch_bounds__(256) void graph_kernel(
    const int* __restrict__ idx_diag, const int* __restrict__ idx_proc,
    const int* __restrict__ idx_med,
    const float* __restrict__ adj_diag, const float* __restrict__ adj_proc,
    const float* __restrict__ adj_med,
    const float* __restrict__ w_dm, const float* __restrict__ w_pm,
    const float* __restrict__ rho,
    const float* __restrict__ HEd, const float* __restrict__ HEp,
    const float* __restrict__ HEm,
    const float* __restrict__ Temd, const float* __restrict__ Temp_,
    const float* __restrict__ Tedm, const float* __restrict__ Tepm,
    float* __restrict__ seq)
{
    __shared__ __align__(16) float hbuf[NDm * HP];
    __shared__ float Sbuf[NDm * 33];
    __shared__ float abuf[NDm * 33];
    __shared__ float wdm[NDm * NMm];
    __shared__ float wpm[NPm * NMm];
    __shared__ float csm[NDm];
    __shared__ float gd[NMm], gp[NMm], fd[NDm], fp[NPm];
    __shared__ float rsd[NDm], csd[NMm], rsp[NPm], csp[NMm];
    __shared__ int sidx_d[NDm], sidx_p[NPm], sidx_m[NMm];
    __shared__ float srho[6];

    int tid = threadIdx.x;
    int row = blockIdx.x;
    int v = row % VV;

    if (tid < NDm) sidx_d[tid] = idx_diag[(long)row * NDm + tid];
    if (tid < NPm) sidx_p[tid] = idx_proc[(long)row * NPm + tid];
    if (tid < NMm) sidx_m[tid] = (v > 0) ? idx_med[(long)(row - 1) * NMm + tid] : 0;
    if (tid < 6) srho[tid] = rho[tid];
    __syncthreads();

    float od_ = homo_phase(HEd, sidx_d, adj_diag + (long)row * NDm * NDm, NDm,
                           hbuf, Sbuf, abuf, csm, tid);
    float op_ = homo_phase(HEp, sidx_p, adj_proc + (long)row * NPm * NPm, NPm,
                           hbuf, Sbuf, abuf, csm, tid);
    float om_ = 0.0f, hd2 = 0.0f, hp2 = 0.0f, hm2 = 0.0f;

    if (v > 0) {
        om_ = homo_phase(HEm, sidx_m, adj_med + (long)row * NMm * NMm, NMm,
                         hbuf, Sbuf, abuf, csm, tid);

        for (int i = tid; i < NDm * NMm; i += 256) wdm[i] = w_dm[(long)row * NDm * NMm + i];
        for (int i = tid; i < NPm * NMm; i += 256) wpm[i] = w_pm[(long)row * NPm * NMm + i];
        __syncthreads();

        if (tid < NDm) {
            float s = 0; for (int m = 0; m < NMm; m++) s += wdm[tid * NMm + m];
            rsd[tid] = s;
        }
        if (tid >= 32 && tid < 32 + NMm) {
            int m = tid - 32; float s = 0;
            for (int n = 0; n < NDm; n++) s += wdm[n * NMm + m];
            csd[m] = s;
        }
        if (tid >= 64 && tid < 64 + NPm) {
            int n = tid - 64; float s = 0;
            for (int m = 0; m < NMm; m++) s += wpm[n * NMm + m];
            rsp[n] = s;
        }
        if (tid >= 96 && tid < 96 + NMm) {
            int m = tid - 96; float s = 0;
            for (int n = 0; n < NPm; n++) s += wpm[n * NMm + m];
            csp[m] = s;
        }
        __syncthreads();

        if (tid < NMm) {
            float s = 0;
            for (int n = 0; n < NDm; n++) s += wdm[n * NMm + tid] / (rsd[n] + 1e-8f);
            gd[tid] = s;
        }
        if (tid >= 32 && tid < 32 + NDm) {
            int n = tid - 32; float s = 0;
            for (int m = 0; m < NMm; m++) s += wdm[n * NMm + m] / (csd[m] + 1e-8f);
            fd[n] = s;
        }
        if (tid >= 64 && tid < 64 + NMm) {
            int m = tid - 64; float s = 0;
            for (int n = 0; n < NPm; n++) s += wpm[n * NMm + m] / (rsp[n] + 1e-8f);
            gp[m] = s;
        }
        if (tid >= 96 && tid < 96 + NPm) {
            int n = tid - 96; float s = 0;
            for (int m = 0; m < NMm; m++) s += wpm[n * NMm + m] / (csp[m] + 1e-8f);
            fp[n] = s;
        }
        __syncthreads();

        for (int m = 0; m < NMm; m++) {
            long base = (long)sidx_m[m] * DD + tid;
            hd2 += gd[m] * Temd[base];
            hp2 += gp[m] * Temp_[base];
        }
        for (int n = 0; n < NDm; n++) hm2 += fd[n] * Tedm[(long)sidx_d[n] * DD + tid];
        for (int n = 0; n < NPm; n++) hm2 += fp[n] * Tepm[(long)sidx_p[n] * DD + tid];
    }

    long o = (long)row * DD + tid;
    seq[o]                 = srho[0] * od_ + srho[1] * hd2;
    seq[2097152L + o]      = srho[2] * op_ + srho[3] * hp2;
    seq[2L * 2097152L + o] = srho[4] * om_ + srho[5] * hm2;
}

// ---------------- TF32 tensor-core GEMM (TN): C = A @ B^T + bias --------------
// A[M,K], B[N,K] row-major fp32; M%128==0, N%128==0, K%32==0.
// 256 threads = 8 warps in 2(m) x 4(n); warp tile 64x32; mma m16n8k8 tf32.
#define TS 36   // padded smem k-stride

__global__ __launch_bounds__(256, 2) void tgemm_tn(
    const float* __restrict__ A, long Az,
    const float* __restrict__ Bm, long Bz,
    const float* __restrict__ bias, long biasz,
    float* __restrict__ C, long Cz,
    int M, int N, int K)
{
    A += (long)blockIdx.z * Az;
    Bm += (long)blockIdx.z * Bz;
    C += (long)blockIdx.z * Cz;
    const float* bi = bias + (long)blockIdx.z * biasz;

    __shared__ uint32_t As[128 * TS];
    __shared__ uint32_t Bs[128 * TS];

    int tid = threadIdx.x;
    int warp = tid >> 5, l = tid & 31;
    int wm = warp >> 2, wn = warp & 3;
    int m0 = blockIdx.y * 128, n0 = blockIdx.x * 128;

    int lrow = tid >> 1;
    int lcol = (tid & 1) * 16;

    const float* Ag = A + (long)(m0 + lrow) * K + lcol;
    const float* Bg = Bm + (long)(n0 + lrow) * K + lcol;

    float acc[4][4][4];
#pragma unroll
    for (int i = 0; i < 4; i++)
#pragma unroll
        for (int j = 0; j < 4; j++)
#pragma unroll
            for (int c = 0; c < 4; c++) acc[i][j][c] = 0.0f;

    int lq = l >> 2;      // 0..7
    int lk = l & 3;       // 0..3

    int T = K >> 5;
    for (int t = 0; t < T; t++) {
        // global -> tf32 -> smem
#pragma unroll
        for (int c = 0; c < 4; c++) {
            float4 va = *(const float4*)(Ag + t * 32 + c * 4);
            float4 vb = *(const float4*)(Bg + t * 32 + c * 4);
            uint32_t* as = &As[lrow * TS + lcol + c * 4];
            uint32_t* bs = &Bs[lrow * TS + lcol + c * 4];
            as[0] = f2tf32(va.x); as[1] = f2tf32(va.y);
            as[2] = f2tf32(va.z); as[3] = f2tf32(va.w);
            bs[0] = f2tf32(vb.x); bs[1] = f2tf32(vb.y);
            bs[2] = f2tf32(vb.z); bs[3] = f2tf32(vb.w);
        }
        __syncthreads();

#pragma unroll
        for (int kk = 0; kk < 32; kk += 8) {
            uint32_t af[4][4], bf[4][2];
#pragma unroll
            for (int i = 0; i < 4; i++) {
                int ar = wm * 64 + i * 16 + lq;
                af[i][0] = As[ar * TS + kk + lk];
                af[i][1] = As[(ar + 8) * TS + kk + lk];
                af[i][2] = As[ar * TS + kk + lk + 4];
                af[i][3] = As[(ar + 8) * TS + kk + lk + 4];
            }
#pragma unroll
            for (int j = 0; j < 4; j++) {
                int br = wn * 32 + j * 8 + lq;
                bf[j][0] = Bs[br * TS + kk + lk];
                bf[j][1] = Bs[br * TS + kk + lk + 4];
            }
#pragma unroll
            for (int i = 0; i < 4; i++)
#pragma unroll
                for (int j = 0; j < 4; j++) {
                    asm volatile(
                        "mma.sync.aligned.m16n8k8.row.col.f32.tf32.tf32.f32 "
                        "{%0,%1,%2,%3}, {%4,%5,%6,%7}, {%8,%9}, {%0,%1,%2,%3};"
                        : "+f"(acc[i][j][0]), "+f"(acc[i][j][1]),
                          "+f"(acc[i][j][2]), "+f"(acc[i][j][3])
                        : "r"(af[i][0]), "r"(af[i][1]), "r"(af[i][2]), "r"(af[i][3]),
                          "r"(bf[j][0]), "r"(bf[j][1]));
                }
        }
        __syncthreads();
    }

    // epilogue
#pragma unroll
    for (int i = 0; i < 4; i++) {
        int r0 = m0 + wm * 64 + i * 16 + lq;
#pragma unroll
        for (int j = 0; j < 4; j++) {
            int c0 = n0 + wn * 32 + j * 8 + 2 * lk;
            float b0 = bi[c0], b1 = bi[c0 + 1];
            *(float2*)&C[(long)r0 * N + c0] =
                make_float2(acc[i][j][0] + b0, acc[i][j][1] + b1);
            *(float2*)&C[(long)(r0 + 8) * N + c0] =
                make_float2(acc[i][j][2] + b0, acc[i][j][3] + b1);
        }
    }
}

// ---------------- GRU gate kernels ----------------
__global__ void gate0_kernel(const float* __restrict__ gi, const float* __restrict__ bhh,
                             float* __restrict__ h)
{
    int idx = blockIdx.x * 256 + threadIdx.x;
    int r = idx >> 18;
    int rem = idx & 262143;
    int b = rem >> 8;
    int d = rem & 255;
    const float* girow = gi + ((long)r * 8192 + (long)b * VV) * 768;
    const float* bh = bhh + (long)r * 768;
    float z  = sigm(girow[256 + d] + bh[256 + d]);
    float rr = sigm(girow[d] + bh[d]);
    float n  = tanhf(girow[512 + d] + rr * bh[512 + d]);
    h[idx] = (1.0f - z) * n;
}

__global__ void gate_kernel(const float* __restrict__ gi, const float* __restrict__ gh,
                            float* __restrict__ h, int v)
{
    int idx = blockIdx.x * 256 + threadIdx.x;
    int r = idx >> 18;
    int rem = idx & 262143;
    int b = rem >> 8;
    int d = rem & 255;
    const float* girow = gi + ((long)r * 8192 + (long)b * VV + v) * 768;
    const float* ghrow = gh + ((long)r * 1024 + b) * 768;
    float hold = h[idx];
    float rr = sigm(girow[d] + ghrow[d]);
    float z  = sigm(girow[256 + d] + ghrow[256 + d]);
    float n  = tanhf(girow[512 + d] + rr * ghrow[512 + d]);
    h[idx] = (1.0f - z) * n + z * hold;
}

__global__ void relu_assemble_kernel(const float* __restrict__ h, float* __restrict__ Hr)
{
    int idx = blockIdx.x * 256 + threadIdx.x;
    int r = idx >> 18;
    int rem = idx & 262143;
    int b = rem >> 8;
    int d = rem & 255;
    Hr[(long)b * 768 + r * 256 + d] = fmaxf(h[idx], 0.0f);
}

__global__ void final1_kernel(const float* __restrict__ scorepad,
                              const float* __restrict__ ddi,
                              float* __restrict__ out, float* __restrict__ partials)
{
    __shared__ float p[VOC_M];
    __shared__ float red[256];
    int b = blockIdx.x, tid = threadIdx.x;
    if (tid < VOC_M) {
        float s = scorepad[(long)b * 256 + tid];
        out[(long)b * VOC_M + tid] = s;
        p[tid] = sigm(s);
    }
    __syncthreads();
    float part = 0.0f;
    if (tid < VOC_M) {
        float inner = 0.0f;
        for (int i = 0; i < VOC_M; i++) inner += p[i] * ddi[(long)i * VOC_M + tid];
        part = p[tid] * inner;
    }
    red[tid] = part;
    __syncthreads();
    for (int s = 128; s > 0; s >>= 1) {
        if (tid < s) red[tid] += red[tid + s];
        __syncthreads();
    }
    if (tid == 0) partials[b] = red[0];
}

__global__ void final2_kernel(const float* __restrict__ partials,
                              float* __restrict__ out, int out_size)
{
    __shared__ float red[256];
    int tid = threadIdx.x;
    float s = partials[tid] + partials[tid + 256] + partials[tid + 512] + partials[tid + 768];
    red[tid] = s;
    __syncthreads();
    for (int st = 128; st > 0; st >>= 1) {
        if (tid < st) red[tid] += red[tid + st];
        __syncthreads();
    }
    if (tid == 0 && out_size > BB * VOC_M) out[BB * VOC_M] = 0.0005f * red[0];
}

// ---------------- host launch ----------------
extern "C" void kernel_launch(void* const* d_in, const int* in_sizes, int n_in,
                              void* d_out, int out_size)
{
    const int* idx_diag = (const int*)d_in[0];
    const int* idx_proc = (const int*)d_in[1];
    const int* idx_med  = (const int*)d_in[2];
    const float* adj_diag = (const float*)d_in[3];
    const float* adj_proc = (const float*)d_in[4];
    const float* adj_med  = (const float*)d_in[5];
    const float* w_dm = (const float*)d_in[6];
    const float* w_pm = (const float*)d_in[7];
    const float* E_diag = (const float*)d_in[8];
    const float* E_proc = (const float*)d_in[9];
    const float* E_med  = (const float*)d_in[10];
    const float* W_homo = (const float*)d_in[11];
    const float* Wh_d  = (const float*)d_in[12];
    const float* Wh_p  = (const float*)d_in[13];
    const float* Wh_md = (const float*)d_in[14];
    const float* Wh_mp = (const float*)d_in[15];
    const float* rho   = (const float*)d_in[16];
    const float* gru_wih = (const float*)d_in[17];
    const float* gru_whh = (const float*)d_in[18];
    const float* gru_bih = (const float*)d_in[19];
    const float* gru_bhh = (const float*)d_in[20];
    const float* Wq = (const float*)d_in[21];
    const float* bq = (const float*)d_in[22];
    const float* ddi = (const float*)d_in[23];

    void* sp = nullptr;
    cudaGetSymbolAddress(&sp, g_scratch);
    float* S = (float*)sp;

    float* HEd   = S + OFF_HED;
    float* HEp   = S + OFF_HEP;
    float* HEm   = S + OFF_HEM;
    float* Temd  = S + OFF_TEMD;
    float* Temp_ = S + OFF_TEMP;
    float* Tedm  = S + OFF_TEDM;
    float* Tepm  = S + OFF_TEPM;
    float* seq   = S + OFF_SEQ;
    float* gi    = S + OFF_GI;
    float* h     = S + OFF_H;
    float* gh    = S + OFF_GH;
    float* Hr    = S + OFF_HR;
    float* Wq2p  = S + OFF_WQ2;
    float* bqp   = S + OFF_BQP;
    float* spad  = S + OFF_SP;
    float* part  = S + OFF_PART;

    // 1) tables
    tables_kernel<<<721, 256>>>(E_diag, E_proc, E_med, W_homo, Wh_d, Wh_p, Wh_md, Wh_mp,
                                Wq, bq, HEd, HEp, HEm, Temd, Temp_, Tedm, Tepm, Wq2p, bqp);

    // 2) fused per-visit graph kernel
    graph_kernel<<<BB * VV, 256>>>(idx_diag, idx_proc, idx_med,
                                   adj_diag, adj_proc, adj_med, w_dm, w_pm, rho,
                                   HEd, HEp, HEm, Temd, Temp_, Tedm, Tepm, seq);

    // 3) gi = seq @ wih^T + bih  (tf32 tensor cores)
    tgemm_tn<<<dim3(6, 64, 3), 256>>>(seq, 8192L * 256, gru_wih, 768L * 256,
                                      gru_bih, 768, gi, 8192L * 768,
                                      8192, 768, 256);

    // 4) GRU recurrence
    gate0_kernel<<<3072, 256>>>(gi, gru_bhh, h);
    for (int v = 1; v < VV; v++) {
        tgemm_tn<<<dim3(6, 8, 3), 256>>>(h, 1024L * 256, gru_whh, 768L * 256,
                                         gru_bhh, 768, gh, 1024L * 768,
                                         1024, 768, 256);
        gate_kernel<<<3072, 256>>>(gi, gh, h, v);
    }

    // 5) final score GEMM
    relu_assemble_kernel<<<3072, 256>>>(h, Hr);
    tgemm_tn<<<dim3(2, 8, 1), 256>>>(Hr, 0, Wq2p, 0, bqp, 0, spad, 0,
                                     1024, 256, 768);

    // 6) outputs
    final1_kernel<<<BB, 256>>>(spad, ddi, (float*)d_out, part);
    final2_kernel<<<1, 256>>>(part, (float*)d_out, out_size);
}

// round 4
// speedup vs baseline: 2.1489x; 1.4875x over previous
#include <cuda_runtime.h>
#include <cstdint>

#define BB 1024
#define VV 8
#define NDm 32
#define NPm 16
#define NMm 24
#define DD 256
#define VOC_D 2000
#define VOC_P 1500
#define VOC_M 131

// ---------------- scratch layout (floats) ----------------
#define OFF_HED   0L
#define OFF_HEP   512000L
#define OFF_HEM   896000L
#define OFF_TEMD  929536L
#define OFF_TEMP  963072L
#define OFF_TEDM  996608L
#define OFF_TEPM  1508608L
#define OFF_SEQ   1892608L        // [3][8192][256]
#define OFF_GI    8184064L        // [3][8192][768]
#define OFF_H     27058432L       // [3][1024][256]
#define OFF_GH    27844864L       // [3][1024][768]
#define OFF_HR    30204160L       // [1024][768]
#define OFF_WQ2   30990592L       // [256][768]
#define OFF_BQP   31187200L       // [256]
#define OFF_SP    31187456L       // [1024][256]
#define OFF_PART  31449600L       // [1024]
#define SCRATCH_TOTAL 31450624L

__device__ __align__(256) float g_scratch[SCRATCH_TOTAL];

__device__ __forceinline__ float sigm(float x) { return 1.0f / (1.0f + expf(-x)); }
__device__ __forceinline__ uint32_t f2tf32(float x) {
    uint32_t r;
    asm("cvt.rna.tf32.f32 %0, %1;" : "=r"(r) : "f"(x));
    return r;
}

// ---------------- Fused table precompute: 7 jobs + Wq2 fold ----------------
__global__ __launch_bounds__(256) void tables_kernel(
    const float* __restrict__ E_diag, const float* __restrict__ E_proc,
    const float* __restrict__ E_med,  const float* __restrict__ W_homo,
    const float* __restrict__ Wh_d,   const float* __restrict__ Wh_p,
    const float* __restrict__ Wh_md,  const float* __restrict__ Wh_mp,
    const float* __restrict__ Wq,     const float* __restrict__ bq,
    float* __restrict__ HEd, float* __restrict__ HEp, float* __restrict__ HEm,
    float* __restrict__ Temd, float* __restrict__ Temp_,
    float* __restrict__ Tedm, float* __restrict__ Tepm,
    float* __restrict__ Wq2p, float* __restrict__ bqp)
{
    int blk = blockIdx.x;
    int tid = threadIdx.x;

    if (blk >= 465) {                         // ---- Wq2 fold ----
        int j = blk - 465;
        for (int c = tid; c < 768; c += 256) {
            float v = 0.0f;
            if (j < VOC_M) v = Wq[(long)j * 1536 + c] + Wq[(long)j * 1536 + 768 + c];
            Wq2p[(long)j * 768 + c] = v;
        }
        if (tid == 0) bqp[j] = (j < VOC_M) ? bq[j] : 0.0f;
        return;
    }

    const float* E; const float* W; float* dst; int rows; int r0;
    if (blk < 125)      { E = E_diag; W = W_homo;          dst = HEd;   rows = VOC_D; r0 = blk * 16; }
    else if (blk < 219) { E = E_proc; W = W_homo + 65536;  dst = HEp;   rows = VOC_P; r0 = (blk-125)*16; }
    else if (blk < 228) { E = E_med;  W = W_homo + 131072; dst = HEm;   rows = VOC_M; r0 = (blk-219)*16; }
    else if (blk < 237) { E = E_med;  W = Wh_d;            dst = Temd;  rows = VOC_M; r0 = (blk-228)*16; }
    else if (blk < 246) { E = E_med;  W = Wh_p;            dst = Temp_; rows = VOC_M; r0 = (blk-237)*16; }
    else if (blk < 371) { E = E_diag; W = Wh_md;           dst = Tedm;  rows = VOC_D; r0 = (blk-246)*16; }
    else                { E = E_proc; W = Wh_mp;           dst = Tepm;  rows = VOC_P; r0 = (blk-371)*16; }

    __shared__ __align__(16) float e[16][DD];
    for (int i = tid; i < 16 * (DD / 4); i += 256) {
        int rr = i >> 6;
        int cc = (i & 63) << 2;
        float4 v = make_float4(0.f, 0.f, 0.f, 0.f);
        if (r0 + rr < rows) v = *(const float4*)&E[(long)(r0 + rr) * DD + cc];
        *(float4*)&e[rr][cc] = v;
    }
    __syncthreads();

    float acc[16];
#pragma unroll
    for (int i = 0; i < 16; i++) acc[i] = 0.0f;
#pragma unroll 4
    for (int k = 0; k < DD; k++) {
        float w = W[(long)k * DD + tid];
#pragma unroll
        for (int i = 0; i < 16; i++) acc[i] += e[i][k] * w;
    }
#pragma unroll
    for (int i = 0; i < 16; i++)
        if (r0 + i < rows) dst[(long)(r0 + i) * DD + tid] = acc[i];
}

// ---------------- per-(b,v) fused graph kernel ----------------
#define HP 260

// Gram via tf32 tensor cores + masked softmax + colsum-weighted rowsum.
__device__ float homo_phase(const float* __restrict__ table, const int* sidx,
                            const float* __restrict__ adjg, int N,
                            float* hbuf, float* Sbuf, float* abuf, float* csm, int tid)
{
    // vectorized gather of h rows
    for (int i = tid; i < N * 64; i += 256) {
        int r = i >> 6, c4 = (i & 63) << 2;
        *(float4*)&hbuf[r * HP + c4] = *(const float4*)&table[(long)sidx[r] * DD + c4];
    }
    for (int i = tid; i < N * N; i += 256)
        abuf[(i / N) * 33 + (i % N)] = adjg[i];
    __syncthreads();

    // S = h h^T / 16 via mma.m16n8k8 tf32; one 16x8 tile per warp
    int warp = tid >> 5, l = tid & 31;
    int tn_n = (N + 7) >> 3;                 // n-tiles: 2,3,4
    int ntiles = ((N + 15) >> 4) * tn_n;     // 2, 6, 8
    if (warp < ntiles) {
        int wm = warp / tn_n, wn = warp % tn_n;
        int lq = l >> 2, lk = l & 3;
        const float* Ab = &hbuf[(wm * 16 + lq) * HP + lk];
        const float* Bb = &hbuf[(wn * 8 + lq) * HP + lk];
        float c0 = 0.f, c1 = 0.f, c2 = 0.f, c3 = 0.f;
#pragma unroll 4
        for (int k = 0; k < DD; k += 8) {
            uint32_t a0 = f2tf32(Ab[k]);
            uint32_t a1 = f2tf32(Ab[8 * HP + k]);
            uint32_t a2 = f2tf32(Ab[k + 4]);
            uint32_t a3 = f2tf32(Ab[8 * HP + k + 4]);
            uint32_t b0 = f2tf32(Bb[k]);
            uint32_t b1 = f2tf32(Bb[k + 4]);
            asm volatile(
                "mma.sync.aligned.m16n8k8.row.col.f32.tf32.tf32.f32 "
                "{%0,%1,%2,%3}, {%4,%5,%6,%7}, {%8,%9}, {%0,%1,%2,%3};"
                : "+f"(c0), "+f"(c1), "+f"(c2), "+f"(c3)
                : "r"(a0), "r"(a1), "r"(a2), "r"(a3), "r"(b0), "r"(b1));
        }
        int r0 = wm * 16 + lq, cc = wn * 8 + 2 * lk;
        Sbuf[r0 * 33 + cc]           = c0 * 0.0625f;
        Sbuf[r0 * 33 + cc + 1]       = c1 * 0.0625f;
        Sbuf[(r0 + 8) * 33 + cc]     = c2 * 0.0625f;
        Sbuf[(r0 + 8) * 33 + cc + 1] = c3 * 0.0625f;
    }
    __syncthreads();

    // masked softmax over rows (threads 0..N-1)
    if (tid < N) {
        int n = tid;
        float mx = -1e30f;
        for (int m = 0; m < N; m++) {
            bool ok = (abuf[n * 33 + m] > 0.5f) || (m == n);
            if (ok) mx = fmaxf(mx, Sbuf[n * 33 + m]);
        }
        float sum = 0.0f;
        for (int m = 0; m < N; m++) {
            bool ok = (abuf[n * 33 + m] > 0.5f) || (m == n);
            float e = ok ? expf(Sbuf[n * 33 + m] - mx) : 0.0f;
            Sbuf[n * 33 + m] = e;
            sum += e;
        }
        float inv = 1.0f / sum;
        for (int m = 0; m < N; m++) Sbuf[n * 33 + m] *= inv;
    }
    __syncthreads();

    // column sums of attention
    if (tid < N) {
        float c = 0.0f;
        for (int n = 0; n < N; n++) c += Sbuf[n * 33 + tid];
        csm[tid] = c;
    }
    __syncthreads();

    // out[d] = sum_m c[m] * h[m][d]
    float o = 0.0f;
    for (int m = 0; m < N; m++) o += csm[m] * hbuf[m * HP + tid];
    __syncthreads();
    return o;
}

__global__ __launch_bounds__(256) void graph_kernel(
    const int* __restrict__ idx_diag, const int* __restrict__ idx_proc,
    const int* __restrict__ idx_med,
    const float* __restrict__ adj_diag, const float* __restrict__ adj_proc,
    const float* __restrict__ adj_med,
    const float* __restrict__ w_dm, const float* __restrict__ w_pm,
    const float* __restrict__ rho,
    const float* __restrict__ HEd, const float* __restrict__ HEp,
    const float* __restrict__ HEm,
    const float* __restrict__ Temd, const float* __restrict__ Temp_,
    const float* __restrict__ Tedm, const float* __restrict__ Tepm,
    float* __restrict__ seq)
{
    __shared__ __align__(16) float hbuf[NDm * HP];
    __shared__ float Sbuf[NDm * 33];
    __shared__ float abuf[NDm * 33];
    __shared__ float wdm[NDm * NMm];
    __shared__ float wpm[NPm * NMm];
    __shared__ float csm[NDm];
    __shared__ float gd[NMm], gp[NMm], fd[NDm], fp[NPm];
    __shared__ float rsd[NDm], csd[NMm], rsp[NPm], csp[NMm];
    __shared__ int sidx_d[NDm], sidx_p[NPm], sidx_m[NMm];
    __shared__ float srho[6];

    int tid = threadIdx.x;
    int row = blockIdx.x;
    int v = row % VV;

    if (tid < NDm) sidx_d[tid] = idx_diag[(long)row * NDm + tid];
    if (tid < NPm) sidx_p[tid] = idx_proc[(long)row * NPm + tid];
    if (tid < NMm) sidx_m[tid] = (v > 0) ? idx_med[(long)(row - 1) * NMm + tid] : 0;
    if (tid < 6) srho[tid] = rho[tid];
    __syncthreads();

    float od_ = homo_phase(HEd, sidx_d, adj_diag + (long)row * NDm * NDm, NDm,
                           hbuf, Sbuf, abuf, csm, tid);
    float op_ = homo_phase(HEp, sidx_p, adj_proc + (long)row * NPm * NPm, NPm,
                           hbuf, Sbuf, abuf, csm, tid);
    float om_ = 0.0f, hd2 = 0.0f, hp2 = 0.0f, hm2 = 0.0f;

    if (v > 0) {
        om_ = homo_phase(HEm, sidx_m, adj_med + (long)row * NMm * NMm, NMm,
                         hbuf, Sbuf, abuf, csm, tid);

        for (int i = tid; i < NDm * NMm; i += 256) wdm[i] = w_dm[(long)row * NDm * NMm + i];
        for (int i = tid; i < NPm * NMm; i += 256) wpm[i] = w_pm[(long)row * NPm * NMm + i];
        __syncthreads();

        if (tid < NDm) {
            float s = 0; for (int m = 0; m < NMm; m++) s += wdm[tid * NMm + m];
            rsd[tid] = s;
        }
        if (tid >= 32 && tid < 32 + NMm) {
            int m = tid - 32; float s = 0;
            for (int n = 0; n < NDm; n++) s += wdm[n * NMm + m];
            csd[m] = s;
        }
        if (tid >= 64 && tid < 64 + NPm) {
            int n = tid - 64; float s = 0;
            for (int m = 0; m < NMm; m++) s += wpm[n * NMm + m];
            rsp[n] = s;
        }
        if (tid >= 96 && tid < 96 + NMm) {
            int m = tid - 96; float s = 0;
            for (int n = 0; n < NPm; n++) s += wpm[n * NMm + m];
            csp[m] = s;
        }
        __syncthreads();

        if (tid < NMm) {
            float s = 0;
            for (int n = 0; n < NDm; n++) s += wdm[n * NMm + tid] / (rsd[n] + 1e-8f);
            gd[tid] = s;
        }
        if (tid >= 32 && tid < 32 + NDm) {
            int n = tid - 32; float s = 0;
            for (int m = 0; m < NMm; m++) s += wdm[n * NMm + m] / (csd[m] + 1e-8f);
            fd[n] = s;
        }
        if (tid >= 64 && tid < 64 + NMm) {
            int m = tid - 64; float s = 0;
            for (int n = 0; n < NPm; n++) s += wpm[n * NMm + m] / (rsp[n] + 1e-8f);
            gp[m] = s;
        }
        if (tid >= 96 && tid < 96 + NPm) {
            int n = tid - 96; float s = 0;
            for (int m = 0; m < NMm; m++) s += wpm[n * NMm + m] / (csp[m] + 1e-8f);
            fp[n] = s;
        }
        __syncthreads();

        for (int m = 0; m < NMm; m++) {
            long base = (long)sidx_m[m] * DD + tid;
            hd2 += gd[m] * Temd[base];
            hp2 += gp[m] * Temp_[base];
        }
        for (int n = 0; n < NDm; n++) hm2 += fd[n] * Tedm[(long)sidx_d[n] * DD + tid];
        for (int n = 0; n < NPm; n++) hm2 += fp[n] * Tepm[(long)sidx_p[n] * DD + tid];
    }

    long o = (long)row * DD + tid;
    seq[o]                 = srho[0] * od_ + srho[1] * hd2;
    seq[2097152L + o]      = srho[2] * op_ + srho[3] * hp2;
    seq[2L * 2097152L + o] = srho[4] * om_ + srho[5] * hm2;
}

// ---------------- TF32 tensor-core GEMM (TN): C = A @ B^T + bias --------------
#define TS 36

__global__ __launch_bounds__(256, 2) void tgemm_tn(
    const float* __restrict__ A, long Az,
    const float* __restrict__ Bm, long Bz,
    const float* __restrict__ bias, long biasz,
    float* __restrict__ C, long Cz,
    int M, int N, int K)
{
    A += (long)blockIdx.z * Az;
    Bm += (long)blockIdx.z * Bz;
    C += (long)blockIdx.z * Cz;
    const float* bi = bias + (long)blockIdx.z * biasz;

    __shared__ uint32_t As[128 * TS];
    __shared__ uint32_t Bs[128 * TS];

    int tid = threadIdx.x;
    int warp = tid >> 5, l = tid & 31;
    int wm = warp >> 2, wn = warp & 3;
    int m0 = blockIdx.y * 128, n0 = blockIdx.x * 128;

    int lrow = tid >> 1;
    int lcol = (tid & 1) * 16;

    const float* Ag = A + (long)(m0 + lrow) * K + lcol;
    const float* Bg = Bm + (long)(n0 + lrow) * K + lcol;

    float acc[4][4][4];
#pragma unroll
    for (int i = 0; i < 4; i++)
#pragma unroll
        for (int j = 0; j < 4; j++)
#pragma unroll
            for (int c = 0; c < 4; c++) acc[i][j][c] = 0.0f;

    int lq = l >> 2;
    int lk = l & 3;

    int T = K >> 5;
    for (int t = 0; t < T; t++) {
#pragma unroll
        for (int c = 0; c < 4; c++) {
            float4 va = *(const float4*)(Ag + t * 32 + c * 4);
            float4 vb = *(const float4*)(Bg + t * 32 + c * 4);
            uint32_t* as = &As[lrow * TS + lcol + c * 4];
            uint32_t* bs = &Bs[lrow * TS + lcol + c * 4];
            as[0] = f2tf32(va.x); as[1] = f2tf32(va.y);
            as[2] = f2tf32(va.z); as[3] = f2tf32(va.w);
            bs[0] = f2tf32(vb.x); bs[1] = f2tf32(vb.y);
            bs[2] = f2tf32(vb.z); bs[3] = f2tf32(vb.w);
        }
        __syncthreads();

#pragma unroll
        for (int kk = 0; kk < 32; kk += 8) {
            uint32_t af[4][4], bf[4][2];
#pragma unroll
            for (int i = 0; i < 4; i++) {
                int ar = wm * 64 + i * 16 + lq;
                af[i][0] = As[ar * TS + kk + lk];
                af[i][1] = As[(ar + 8) * TS + kk + lk];
                af[i][2] = As[ar * TS + kk + lk + 4];
                af[i][3] = As[(ar + 8) * TS + kk + lk + 4];
            }
#pragma unroll
            for (int j = 0; j < 4; j++) {
                int br = wn * 32 + j * 8 + lq;
                bf[j][0] = Bs[br * TS + kk + lk];
                bf[j][1] = Bs[br * TS + kk + lk + 4];
            }
#pragma unroll
            for (int i = 0; i < 4; i++)
#pragma unroll
                for (int j = 0; j < 4; j++) {
                    asm volatile(
                        "mma.sync.aligned.m16n8k8.row.col.f32.tf32.tf32.f32 "
                        "{%0,%1,%2,%3}, {%4,%5,%6,%7}, {%8,%9}, {%0,%1,%2,%3};"
                        : "+f"(acc[i][j][0]), "+f"(acc[i][j][1]),
                          "+f"(acc[i][j][2]), "+f"(acc[i][j][3])
                        : "r"(af[i][0]), "r"(af[i][1]), "r"(af[i][2]), "r"(af[i][3]),
                          "r"(bf[j][0]), "r"(bf[j][1]));
                }
        }
        __syncthreads();
    }

#pragma unroll
    for (int i = 0; i < 4; i++) {
        int r0 = m0 + wm * 64 + i * 16 + lq;
#pragma unroll
        for (int j = 0; j < 4; j++) {
            int c0 = n0 + wn * 32 + j * 8 + 2 * lk;
            float b0 = bi[c0], b1 = bi[c0 + 1];
            *(float2*)&C[(long)r0 * N + c0] =
                make_float2(acc[i][j][0] + b0, acc[i][j][1] + b1);
            *(float2*)&C[(long)(r0 + 8) * N + c0] =
                make_float2(acc[i][j][2] + b0, acc[i][j][3] + b1);
        }
    }
}

// ---------------- GRU gate kernels ----------------
__global__ void gate0_kernel(const float* __restrict__ gi, const float* __restrict__ bhh,
                             float* __restrict__ h)
{
    int idx = blockIdx.x * 256 + threadIdx.x;
    int r = idx >> 18;
    int rem = idx & 262143;
    int b = rem >> 8;
    int d = rem & 255;
    const float* girow = gi + ((long)r * 8192 + (long)b * VV) * 768;
    const float* bh = bhh + (long)r * 768;
    float z  = sigm(girow[256 + d] + bh[256 + d]);
    float rr = sigm(girow[d] + bh[d]);
    float n  = tanhf(girow[512 + d] + rr * bh[512 + d]);
    h[idx] = (1.0f - z) * n;
}

__global__ void gate_kernel(const float* __restrict__ gi, const float* __restrict__ gh,
                            float* __restrict__ h, int v,
                            float* __restrict__ Hr, int last)
{
    int idx = blockIdx.x * 256 + threadIdx.x;
    int r = idx >> 18;
    int rem = idx & 262143;
    int b = rem >> 8;
    int d = rem & 255;
    const float* girow = gi + ((long)r * 8192 + (long)b * VV + v) * 768;
    const float* ghrow = gh + ((long)r * 1024 + b) * 768;
    float hold = h[idx];
    float rr = sigm(girow[d] + ghrow[d]);
    float z  = sigm(girow[256 + d] + ghrow[256 + d]);
    float n  = tanhf(girow[512 + d] + rr * ghrow[512 + d]);
    float hnew = (1.0f - z) * n + z * hold;
    h[idx] = hnew;
    if (last) Hr[(long)b * 768 + r * 256 + d] = fmaxf(hnew, 0.0f);
}

__global__ void final1_kernel(const float* __restrict__ scorepad,
                              const float* __restrict__ ddi,
                              float* __restrict__ out, float* __restrict__ partials)
{
    __shared__ float p[VOC_M];
    __shared__ float red[256];
    int b = blockIdx.x, tid = threadIdx.x;
    if (tid < VOC_M) {
        float s = scorepad[(long)b * 256 + tid];
        out[(long)b * VOC_M + tid] = s;
        p[tid] = sigm(s);
    }
    __syncthreads();
    float part = 0.0f;
    if (tid < VOC_M) {
        float inner = 0.0f;
        for (int i = 0; i < VOC_M; i++) inner += p[i] * ddi[(long)i * VOC_M + tid];
        part = p[tid] * inner;
    }
    red[tid] = part;
    __syncthreads();
    for (int s = 128; s > 0; s >>= 1) {
        if (tid < s) red[tid] += red[tid + s];
        __syncthreads();
    }
    if (tid == 0) partials[b] = red[0];
}

__global__ void final2_kernel(const float* __restrict__ partials,
                              float* __restrict__ out, int out_size)
{
    __shared__ float red[256];
    int tid = threadIdx.x;
    float s = partials[tid] + partials[tid + 256] + partials[tid + 512] + partials[tid + 768];
    red[tid] = s;
    __syncthreads();
    for (int st = 128; st > 0; st >>= 1) {
        if (tid < st) red[tid] += red[tid + st];
        __syncthreads();
    }
    if (tid == 0 && out_size > BB * VOC_M) out[BB * VOC_M] = 0.0005f * red[0];
}

// ---------------- host launch ----------------
extern "C" void kernel_launch(void* const* d_in, const int* in_sizes, int n_in,
                              void* d_out, int out_size)
{
    const int* idx_diag = (const int*)d_in[0];
    const int* idx_proc = (const int*)d_in[1];
    const int* idx_med  = (const int*)d_in[2];
    const float* adj_diag = (const float*)d_in[3];
    const float* adj_proc = (const float*)d_in[4];
    const float* adj_med  = (const float*)d_in[5];
    const float* w_dm = (const float*)d_in[6];
    const float* w_pm = (const float*)d_in[7];
    const float* E_diag = (const float*)d_in[8];
    const float* E_proc = (const float*)d_in[9];
    const float* E_med  = (const float*)d_in[10];
    const float* W_homo = (const float*)d_in[11];
    const float* Wh_d  = (const float*)d_in[12];
    const float* Wh_p  = (const float*)d_in[13];
    const float* Wh_md = (const float*)d_in[14];
    const float* Wh_mp = (const float*)d_in[15];
    const float* rho   = (const float*)d_in[16];
    const float* gru_wih = (const float*)d_in[17];
    const float* gru_whh = (const float*)d_in[18];
    const float* gru_bih = (const float*)d_in[19];
    const float* gru_bhh = (const float*)d_in[20];
    const float* Wq = (const float*)d_in[21];
    const float* bq = (const float*)d_in[22];
    const float* ddi = (const float*)d_in[23];

    void* sp = nullptr;
    cudaGetSymbolAddress(&sp, g_scratch);
    float* S = (float*)sp;

    float* HEd   = S + OFF_HED;
    float* HEp   = S + OFF_HEP;
    float* HEm   = S + OFF_HEM;
    float* Temd  = S + OFF_TEMD;
    float* Temp_ = S + OFF_TEMP;
    float* Tedm  = S + OFF_TEDM;
    float* Tepm  = S + OFF_TEPM;
    float* seq   = S + OFF_SEQ;
    float* gi    = S + OFF_GI;
    float* h     = S + OFF_H;
    float* gh    = S + OFF_GH;
    float* Hr    = S + OFF_HR;
    float* Wq2p  = S + OFF_WQ2;
    float* bqp   = S + OFF_BQP;
    float* spad  = S + OFF_SP;
    float* part  = S + OFF_PART;

    // 1) tables
    tables_kernel<<<721, 256>>>(E_diag, E_proc, E_med, W_homo, Wh_d, Wh_p, Wh_md, Wh_mp,
                                Wq, bq, HEd, HEp, HEm, Temd, Temp_, Tedm, Tepm, Wq2p, bqp);

    // 2) fused per-visit graph kernel (tensor-core Gram)
    graph_kernel<<<BB * VV, 256>>>(idx_diag, idx_proc, idx_med,
                                   adj_diag, adj_proc, adj_med, w_dm, w_pm, rho,
                                   HEd, HEp, HEm, Temd, Temp_, Tedm, Tepm, seq);

    // 3) gi = seq @ wih^T + bih
    tgemm_tn<<<dim3(6, 64, 3), 256>>>(seq, 8192L * 256, gru_wih, 768L * 256,
                                      gru_bih, 768, gi, 8192L * 768,
                                      8192, 768, 256);

    // 4) GRU recurrence (last step fuses ReLU + repr assembly)
    gate0_kernel<<<3072, 256>>>(gi, gru_bhh, h);
    for (int v = 1; v < VV; v++) {
        tgemm_tn<<<dim3(6, 8, 3), 256>>>(h, 1024L * 256, gru_whh, 768L * 256,
                                         gru_bhh, 768, gh, 1024L * 768,
                                         1024, 768, 256);
        gate_kernel<<<3072, 256>>>(gi, gh, h, v, Hr, v == VV - 1);
    }

    // 5) final score GEMM
    tgemm_tn<<<dim3(2, 8, 1), 256>>>(Hr, 0, Wq2p, 0, bqp, 0, spad, 0,
                                     1024, 256, 768);

    // 6) outputs
    final1_kernel<<<BB, 256>>>(spad, ddi, (float*)d_out, part);
    final2_kernel<<<1, 256>>>(part, (float*)d_out, out_size);
}

// round 7
// speedup vs baseline: 2.2920x; 1.0666x over previous
#include <cuda_runtime.h>
#include <cstdint>

#define BB 1024
#define VV 8
#define NDm 32
#define NPm 16
#define NMm 24
#define DD 256
#define VOC_D 2000
#define VOC_P 1500
#define VOC_M 131

// ---------------- scratch layout (floats) ----------------
#define OFF_HED   0L
#define OFF_HEP   512000L
#define OFF_HEM   896000L
#define OFF_TEMD  929536L
#define OFF_TEMP  963072L
#define OFF_TEDM  996608L
#define OFF_TEPM  1508608L
#define OFF_SEQ   1892608L        // [3][8192][256]
#define OFF_GI    8184064L        // [3][8192][768]
#define OFF_H0    27058432L       // [3][1024][256]
#define OFF_H1    27844864L       // [3][1024][256]
#define OFF_HR    28631296L       // [1024][768]
#define OFF_WQ2   29417728L       // [256][768]
#define OFF_BQP   29614336L       // [256]
#define OFF_SP    29614592L       // [1024][256]
#define OFF_PART  29876736L       // [1024]
#define OFF_WIHP  29877760L       // [3][768][256] permuted
#define OFF_WHHP  30467584L       // [3][768][256] permuted
#define OFF_BIHP  31057408L       // [3][768]
#define OFF_BHHP  31059712L       // [3][768]
#define SCRATCH_TOTAL 31062016L

__device__ __align__(256) float g_scratch[SCRATCH_TOTAL];

__device__ __forceinline__ float sigm(float x) { return 1.0f / (1.0f + expf(-x)); }
__device__ __forceinline__ uint32_t f2tf32(float x) {
    uint32_t r;
    asm("cvt.rna.tf32.f32 %0, %1;" : "=r"(r) : "f"(x));
    return r;
}

// ---------------- Fused precompute: 7 table jobs + Wq2 + GRU weight permutes ----
// [0,465) tables | [465,721) wq2 | [721,1009) wih/whh permute | [1009,1010) biases
__global__ __launch_bounds__(256) void tables_kernel(
    const float* __restrict__ E_diag, const float* __restrict__ E_proc,
    const float* __restrict__ E_med,  const float* __restrict__ W_homo,
    const float* __restrict__ Wh_d,   const float* __restrict__ Wh_p,
    const float* __restrict__ Wh_md,  const float* __restrict__ Wh_mp,
    const float* __restrict__ Wq,     const float* __restrict__ bq,
    const float* __restrict__ gru_wih, const float* __restrict__ gru_whh,
    const float* __restrict__ gru_bih, const float* __restrict__ gru_bhh,
    float* __restrict__ HEd, float* __restrict__ HEp, float* __restrict__ HEm,
    float* __restrict__ Temd, float* __restrict__ Temp_,
    float* __restrict__ Tedm, float* __restrict__ Tepm,
    float* __restrict__ Wq2p, float* __restrict__ bqp,
    float* __restrict__ WIHP, float* __restrict__ WHHP,
    float* __restrict__ BIHP, float* __restrict__ BHHP)
{
    int blk = blockIdx.x;
    int tid = threadIdx.x;

    if (blk >= 1009) {                        // ---- bias permutes ----
        for (int e = tid; e < 2304; e += 256) {
            int z = e / 768, np = e % 768, d = np / 3, g = np % 3;
            BIHP[e] = gru_bih[(long)z * 768 + g * 256 + d];
            BHHP[e] = gru_bhh[(long)z * 768 + g * 256 + d];
        }
        return;
    }
    if (blk >= 721) {                         // ---- weight permutes ----
        int k = blk - 721;                    // 0..287, 16 rows each
        for (int i = 0; i < 16; i++) {
            int gr = k * 16 + i;              // 0..4607
            int t = gr / 2304;
            int rr = gr % 2304;
            int z = rr / 768, np = rr % 768, d = np / 3, g = np % 3;
            const float* src;
            float* dst;
            if (t == 0) {
                src = gru_wih + ((long)z * 768 + g * 256 + d) * 256;
                dst = WIHP + ((long)z * 768 + np) * 256;
            } else {
                src = gru_whh + ((long)z * 768 + g * 256 + d) * 256;
                dst = WHHP + ((long)z * 768 + np) * 256;
            }
            dst[tid] = src[tid];
        }
        return;
    }
    if (blk >= 465) {                         // ---- Wq2 fold ----
        int j = blk - 465;
        for (int c = tid; c < 768; c += 256) {
            float v = 0.0f;
            if (j < VOC_M) v = Wq[(long)j * 1536 + c] + Wq[(long)j * 1536 + 768 + c];
            Wq2p[(long)j * 768 + c] = v;
        }
        if (tid == 0) bqp[j] = (j < VOC_M) ? bq[j] : 0.0f;
        return;
    }

    const float* E; const float* W; float* dst; int rows; int r0;
    if (blk < 125)      { E = E_diag; W = W_homo;          dst = HEd;   rows = VOC_D; r0 = blk * 16; }
    else if (blk < 219) { E = E_proc; W = W_homo + 65536;  dst = HEp;   rows = VOC_P; r0 = (blk-125)*16; }
    else if (blk < 228) { E = E_med;  W = W_homo + 131072; dst = HEm;   rows = VOC_M; r0 = (blk-219)*16; }
    else if (blk < 237) { E = E_med;  W = Wh_d;            dst = Temd;  rows = VOC_M; r0 = (blk-228)*16; }
    else if (blk < 246) { E = E_med;  W = Wh_p;            dst = Temp_; rows = VOC_M; r0 = (blk-237)*16; }
    else if (blk < 371) { E = E_diag; W = Wh_md;           dst = Tedm;  rows = VOC_D; r0 = (blk-246)*16; }
    else                { E = E_proc; W = Wh_mp;           dst = Tepm;  rows = VOC_P; r0 = (blk-371)*16; }

    __shared__ __align__(16) float e[16][DD];
    for (int i = tid; i < 16 * (DD / 4); i += 256) {
        int rr = i >> 6;
        int cc = (i & 63) << 2;
        float4 v = make_float4(0.f, 0.f, 0.f, 0.f);
        if (r0 + rr < rows) v = *(const float4*)&E[(long)(r0 + rr) * DD + cc];
        *(float4*)&e[rr][cc] = v;
    }
    __syncthreads();

    float acc[16];
#pragma unroll
    for (int i = 0; i < 16; i++) acc[i] = 0.0f;
#pragma unroll 4
    for (int k = 0; k < DD; k++) {
        float w = W[(long)k * DD + tid];
#pragma unroll
        for (int i = 0; i < 16; i++) acc[i] += e[i][k] * w;
    }
#pragma unroll
    for (int i = 0; i < 16; i++)
        if (r0 + i < rows) dst[(long)(r0 + i) * DD + tid] = acc[i];
}

// ---------------- per-(b,v) fused graph kernel ----------------
#define HP 260

// Gram via tf32 mma + warp-parallel masked softmax with fused column-sum.
__device__ float homo_phase(const float* __restrict__ table, const int* sidx,
                            const float* __restrict__ adjg, int N,
                            float* hbuf, float* Sbuf, float* pbuf, float* csm, int tid)
{
    // vectorized gather of h rows
    for (int i = tid; i < N * 64; i += 256) {
        int r = i >> 6, c4 = (i & 63) << 2;
        *(float4*)&hbuf[r * HP + c4] = *(const float4*)&table[(long)sidx[r] * DD + c4];
    }
    __syncthreads();

    int warp = tid >> 5, l = tid & 31;

    // S = h h^T / 16 via mma.m16n8k8 tf32; one 16x8 tile per warp
    int tn_n = (N + 7) >> 3;
    int ntiles = ((N + 15) >> 4) * tn_n;
    if (warp < ntiles) {
        int wm = warp / tn_n, wn = warp % tn_n;
        int lq = l >> 2, lk = l & 3;
        const float* Ab = &hbuf[(wm * 16 + lq) * HP + lk];
        const float* Bb = &hbuf[(wn * 8 + lq) * HP + lk];
        float c0 = 0.f, c1 = 0.f, c2 = 0.f, c3 = 0.f;
#pragma unroll 4
        for (int k = 0; k < DD; k += 8) {
            uint32_t a0 = f2tf32(Ab[k]);
            uint32_t a1 = f2tf32(Ab[8 * HP + k]);
            uint32_t a2 = f2tf32(Ab[k + 4]);
            uint32_t a3 = f2tf32(Ab[8 * HP + k + 4]);
            uint32_t b0 = f2tf32(Bb[k]);
            uint32_t b1 = f2tf32(Bb[k + 4]);
            asm volatile(
                "mma.sync.aligned.m16n8k8.row.col.f32.tf32.tf32.f32 "
                "{%0,%1,%2,%3}, {%4,%5,%6,%7}, {%8,%9}, {%0,%1,%2,%3};"
                : "+f"(c0), "+f"(c1), "+f"(c2), "+f"(c3)
                : "r"(a0), "r"(a1), "r"(a2), "r"(a3), "r"(b0), "r"(b1));
        }
        int r0 = wm * 16 + lq, cc = wn * 8 + 2 * lk;
        Sbuf[r0 * 33 + cc]           = c0 * 0.0625f;
        Sbuf[r0 * 33 + cc + 1]       = c1 * 0.0625f;
        Sbuf[(r0 + 8) * 33 + cc]     = c2 * 0.0625f;
        Sbuf[(r0 + 8) * 33 + cc + 1] = c3 * 0.0625f;
    }
    __syncthreads();

    // warp-parallel masked softmax; only column sums are retained
    int rpw = N >> 3;                         // rows per warp: 4/2/3
    float colacc = 0.0f;
    for (int i = 0; i < rpw; i++) {
        int n = warp * rpw + i;
        float a = (l < N) ? adjg[n * N + l] : 0.0f;
        bool ok = (l < N) && ((a > 0.5f) || (l == n));
        float s = ok ? Sbuf[n * 33 + l] : -1e30f;
        float mx = s;
#pragma unroll
        for (int o = 16; o; o >>= 1) mx = fmaxf(mx, __shfl_xor_sync(0xffffffffu, mx, o));
        float e = ok ? expf(s - mx) : 0.0f;
        float sum = e;
#pragma unroll
        for (int o = 16; o; o >>= 1) sum += __shfl_xor_sync(0xffffffffu, sum, o);
        colacc += e / sum;
    }
    pbuf[warp * 33 + l] = colacc;
    __syncthreads();
    if (tid < 32) {
        float c = 0.0f;
#pragma unroll
        for (int w = 0; w < 8; w++) c += pbuf[w * 33 + tid];
        csm[tid] = c;
    }
    __syncthreads();

    // out[d] = sum_m c[m] * h[m][d]
    float o = 0.0f;
    for (int m = 0; m < N; m++) o += csm[m] * hbuf[m * HP + tid];
    __syncthreads();
    return o;
}

__global__ __launch_bounds__(256) void graph_kernel(
    const int* __restrict__ idx_diag, const int* __restrict__ idx_proc,
    const int* __restrict__ idx_med,
    const float* __restrict__ adj_diag, const float* __restrict__ adj_proc,
    const float* __restrict__ adj_med,
    const float* __restrict__ w_dm, const float* __restrict__ w_pm,
    const float* __restrict__ rho,
    const float* __restrict__ HEd, const float* __restrict__ HEp,
    const float* __restrict__ HEm,
    const float* __restrict__ Temd, const float* __restrict__ Temp_,
    const float* __restrict__ Tedm, const float* __restrict__ Tepm,
    float* __restrict__ seq)
{
    __shared__ __align__(16) float hbuf[NDm * HP];
    __shared__ float Sbuf[NDm * 33];
    __shared__ float pbuf[8 * 33];
    __shared__ float wdm[NDm * NMm];
    __shared__ float wpm[NPm * NMm];
    __shared__ float csm[NDm];
    __shared__ float gd[NMm], gp[NMm], fd[NDm], fp[NPm];
    __shared__ float rsd[NDm], csd[NMm], rsp[NPm], csp[NMm];
    __shared__ int sidx_d[NDm], sidx_p[NPm], sidx_m[NMm];
    __shared__ float srho[6];

    int tid = threadIdx.x;
    int row = blockIdx.x;
    int v = row % VV;

    if (tid < NDm) sidx_d[tid] = idx_diag[(long)row * NDm + tid];
    if (tid < NPm) sidx_p[tid] = idx_proc[(long)row * NPm + tid];
    if (tid < NMm) sidx_m[tid] = (v > 0) ? idx_med[(long)(row - 1) * NMm + tid] : 0;
    if (tid < 6) srho[tid] = rho[tid];
    __syncthreads();

    float od_ = homo_phase(HEd, sidx_d, adj_diag + (long)row * NDm * NDm, NDm,
                           hbuf, Sbuf, pbuf, csm, tid);
    float op_ = homo_phase(HEp, sidx_p, adj_proc + (long)row * NPm * NPm, NPm,
                           hbuf, Sbuf, pbuf, csm, tid);
    float om_ = 0.0f, hd2 = 0.0f, hp2 = 0.0f, hm2 = 0.0f;

    if (v > 0) {
        om_ = homo_phase(HEm, sidx_m, adj_med + (long)row * NMm * NMm, NMm,
                         hbuf, Sbuf, pbuf, csm, tid);

        for (int i = tid; i < NDm * NMm; i += 256) wdm[i] = w_dm[(long)row * NDm * NMm + i];
        for (int i = tid; i < NPm * NMm; i += 256) wpm[i] = w_pm[(long)row * NPm * NMm + i];
        __syncthreads();

        if (tid < NDm) {
            float s = 0; for (int m = 0; m < NMm; m++) s += wdm[tid * NMm + m];
            rsd[tid] = s;
        }
        if (tid >= 32 && tid < 32 + NMm) {
            int m = tid - 32; float s = 0;
            for (int n = 0; n < NDm; n++) s += wdm[n * NMm + m];
            csd[m] = s;
        }
        if (tid >= 64 && tid < 64 + NPm) {
            int n = tid - 64; float s = 0;
            for (int m = 0; m < NMm; m++) s += wpm[n * NMm + m];
            rsp[n] = s;
        }
        if (tid >= 96 && tid < 96 + NMm) {
            int m = tid - 96; float s = 0;
            for (int n = 0; n < NPm; n++) s += wpm[n * NMm + m];
            csp[m] = s;
        }
        __syncthreads();

        if (tid < NMm) {
            float s = 0;
            for (int n = 0; n < NDm; n++) s += wdm[n * NMm + tid] / (rsd[n] + 1e-8f);
            gd[tid] = s;
        }
        if (tid >= 32 && tid < 32 + NDm) {
            int n = tid - 32; float s = 0;
            for (int m = 0; m < NMm; m++) s += wdm[n * NMm + m] / (csd[m] + 1e-8f);
            fd[n] = s;
        }
        if (tid >= 64 && tid < 64 + NMm) {
            int m = tid - 64; float s = 0;
            for (int n = 0; n < NPm; n++) s += wpm[n * NMm + m] / (rsp[n] + 1e-8f);
            gp[m] = s;
        }
        if (tid >= 96 && tid < 96 + NPm) {
            int n = tid - 96; float s = 0;
            for (int m = 0; m < NMm; m++) s += wpm[n * NMm + m] / (csp[m] + 1e-8f);
            fp[n] = s;
        }
        __syncthreads();

        for (int m = 0; m < NMm; m++) {
            long base = (long)sidx_m[m] * DD + tid;
            hd2 += gd[m] * Temd[base];
            hp2 += gp[m] * Temp_[base];
        }
        for (int n = 0; n < NDm; n++) hm2 += fd[n] * Tedm[(long)sidx_d[n] * DD + tid];
        for (int n = 0; n < NPm; n++) hm2 += fp[n] * Tepm[(long)sidx_p[n] * DD + tid];
    }

    long o = (long)row * DD + tid;
    seq[o]                 = srho[0] * od_ + srho[1] * hd2;
    seq[2097152L + o]      = srho[2] * op_ + srho[3] * hp2;
    seq[2L * 2097152L + o] = srho[4] * om_ + srho[5] * hm2;
}

// ---------------- TF32 tensor-core GEMM (TN): C = A @ B^T + bias --------------
#define TS 36

__global__ __launch_bounds__(256, 2) void tgemm_tn(
    const float* __restrict__ A, long Az,
    const float* __restrict__ Bm, long Bz,
    const float* __restrict__ bias, long biasz,
    float* __restrict__ C, long Cz,
    int M, int N, int K)
{
    A += (long)blockIdx.z * Az;
    Bm += (long)blockIdx.z * Bz;
    C += (long)blockIdx.z * Cz;
    const float* bi = bias + (long)blockIdx.z * biasz;

    __shared__ uint32_t As[128 * TS];
    __shared__ uint32_t Bs[128 * TS];

    int tid = threadIdx.x;
    int warp = tid >> 5, l = tid & 31;
    int wm = warp >> 2, wn = warp & 3;
    int m0 = blockIdx.y * 128, n0 = blockIdx.x * 128;

    int lrow = tid >> 1;
    int lcol = (tid & 1) * 16;

    const float* Ag = A + (long)(m0 + lrow) * K + lcol;
    const float* Bg = Bm + (long)(n0 + lrow) * K + lcol;

    float acc[4][4][4];
#pragma unroll
    for (int i = 0; i < 4; i++)
#pragma unroll
        for (int j = 0; j < 4; j++)
#pragma unroll
            for (int c = 0; c < 4; c++) acc[i][j][c] = 0.0f;

    int lq = l >> 2;
    int lk = l & 3;

    int T = K >> 5;
    for (int t = 0; t < T; t++) {
#pragma unroll
        for (int c = 0; c < 4; c++) {
            float4 va = *(const float4*)(Ag + t * 32 + c * 4);
            float4 vb = *(const float4*)(Bg + t * 32 + c * 4);
            uint32_t* as = &As[lrow * TS + lcol + c * 4];
            uint32_t* bs = &Bs[lrow * TS + lcol + c * 4];
            as[0] = f2tf32(va.x); as[1] = f2tf32(va.y);
            as[2] = f2tf32(va.z); as[3] = f2tf32(va.w);
            bs[0] = f2tf32(vb.x); bs[1] = f2tf32(vb.y);
            bs[2] = f2tf32(vb.z); bs[3] = f2tf32(vb.w);
        }
        __syncthreads();

#pragma unroll
        for (int kk = 0; kk < 32; kk += 8) {
            uint32_t af[4][4], bf[4][2];
#pragma unroll
            for (int i = 0; i < 4; i++) {
                int ar = wm * 64 + i * 16 + lq;
                af[i][0] = As[ar * TS + kk + lk];
                af[i][1] = As[(ar + 8) * TS + kk + lk];
                af[i][2] = As[ar * TS + kk + lk + 4];
                af[i][3] = As[(ar + 8) * TS + kk + lk + 4];
            }
#pragma unroll
            for (int j = 0; j < 4; j++) {
                int br = wn * 32 + j * 8 + lq;
                bf[j][0] = Bs[br * TS + kk + lk];
                bf[j][1] = Bs[br * TS + kk + lk + 4];
            }
#pragma unroll
            for (int i = 0; i < 4; i++)
#pragma unroll
                for (int j = 0; j < 4; j++) {
                    asm volatile(
                        "mma.sync.aligned.m16n8k8.row.col.f32.tf32.tf32.f32 "
                        "{%0,%1,%2,%3}, {%4,%5,%6,%7}, {%8,%9}, {%0,%1,%2,%3};"
                        : "+f"(acc[i][j][0]), "+f"(acc[i][j][1]),
                          "+f"(acc[i][j][2]), "+f"(acc[i][j][3])
                        : "r"(af[i][0]), "r"(af[i][1]), "r"(af[i][2]), "r"(af[i][3]),
                          "r"(bf[j][0]), "r"(bf[j][1]));
                }
        }
        __syncthreads();
    }

#pragma unroll
    for (int i = 0; i < 4; i++) {
        int r0 = m0 + wm * 64 + i * 16 + lq;
#pragma unroll
        for (int j = 0; j < 4; j++) {
            int c0 = n0 + wn * 32 + j * 8 + 2 * lk;
            float b0 = bi[c0], b1 = bi[c0 + 1];
            *(float2*)&C[(long)r0 * N + c0] =
                make_float2(acc[i][j][0] + b0, acc[i][j][1] + b1);
            *(float2*)&C[(long)(r0 + 8) * N + c0] =
                make_float2(acc[i][j][2] + b0, acc[i][j][3] + b1);
        }
    }
}

// ---------------- fused GRU step: gh GEMM (gate-interleaved) + gates ----------
// grid (8, 8, 3): block = 128 batch rows x 96 gh cols (= 32 complete d-groups)
// gh staged in two 64-row halves (64x100 floats, overlaps As/Bs region).
__global__ __launch_bounds__(256, 2) void gru_step(
    const float* __restrict__ hin, const float* __restrict__ whhp,
    const float* __restrict__ bhhp, const float* __restrict__ gi,
    float* __restrict__ hout, int v, float* __restrict__ Hr, int last)
{
    __shared__ __align__(16) uint32_t smu[128 * TS * 2];   // 36 KB
    uint32_t* As = smu;
    uint32_t* Bs = smu + 128 * TS;
    float* ghs = (float*)smu;                              // 64*100 floats, reused

    int z = blockIdx.z;
    hin  += (long)z * 262144;
    hout += (long)z * 262144;
    whhp += (long)z * 196608;
    const float* bh = bhhp + (long)z * 768;
    gi   += (long)z * 6291456;

    int tid = threadIdx.x;
    int warp = tid >> 5, l = tid & 31;
    int wm = warp >> 2, wn = warp & 3;
    int n0 = blockIdx.x * 96, m0 = blockIdx.y * 128;
    int d0 = blockIdx.x * 32;

    int lrow = tid >> 1, lcol = (tid & 1) * 16;
    const float* Ag = hin + (long)(m0 + lrow) * 256 + lcol;
    const float* Bg = whhp + (long)(n0 + lrow) * 256 + lcol;
    bool bok = lrow < 96;

    float acc[4][3][4];
#pragma unroll
    for (int i = 0; i < 4; i++)
#pragma unroll
        for (int j = 0; j < 3; j++)
#pragma unroll
            for (int c = 0; c < 4; c++) acc[i][j][c] = 0.0f;

    int lq = l >> 2, lk = l & 3;

#pragma unroll 1
    for (int t = 0; t < 8; t++) {
#pragma unroll
        for (int c = 0; c < 4; c++) {
            float4 va = *(const float4*)(Ag + t * 32 + c * 4);
            uint32_t* as = &As[lrow * TS + lcol + c * 4];
            as[0] = f2tf32(va.x); as[1] = f2tf32(va.y);
            as[2] = f2tf32(va.z); as[3] = f2tf32(va.w);
            if (bok) {
                float4 vb = *(const float4*)(Bg + t * 32 + c * 4);
                uint32_t* bs = &Bs[lrow * TS + lcol + c * 4];
                bs[0] = f2tf32(vb.x); bs[1] = f2tf32(vb.y);
                bs[2] = f2tf32(vb.z); bs[3] = f2tf32(vb.w);
            }
        }
        __syncthreads();

#pragma unroll
        for (int kk = 0; kk < 32; kk += 8) {
            uint32_t af[4][4], bf[3][2];
#pragma unroll
            for (int i = 0; i < 4; i++) {
                int ar = wm * 64 + i * 16 + lq;
                af[i][0] = As[ar * TS + kk + lk];
                af[i][1] = As[(ar + 8) * TS + kk + lk];
                af[i][2] = As[ar * TS + kk + lk + 4];
                af[i][3] = As[(ar + 8) * TS + kk + lk + 4];
            }
#pragma unroll
            for (int j = 0; j < 3; j++) {
                int br = wn * 24 + j * 8 + lq;
                bf[j][0] = Bs[br * TS + kk + lk];
                bf[j][1] = Bs[br * TS + kk + lk + 4];
            }
#pragma unroll
            for (int i = 0; i < 4; i++)
#pragma unroll
                for (int j = 0; j < 3; j++) {
                    asm volatile(
                        "mma.sync.aligned.m16n8k8.row.col.f32.tf32.tf32.f32 "
                        "{%0,%1,%2,%3}, {%4,%5,%6,%7}, {%8,%9}, {%0,%1,%2,%3};"
                        : "+f"(acc[i][j][0]), "+f"(acc[i][j][1]),
                          "+f"(acc[i][j][2]), "+f"(acc[i][j][3])
                        : "r"(af[i][0]), "r"(af[i][1]), "r"(af[i][2]), "r"(af[i][3]),
                          "r"(bf[j][0]), "r"(bf[j][1]));
                }
        }
        __syncthreads();
    }

    // two-half staging + gate application (rows [half*64, half*64+64))
#pragma unroll 1
    for (int half = 0; half < 2; half++) {
        if (wm == half) {
#pragma unroll
            for (int i = 0; i < 4; i++) {
                int r0 = i * 16 + lq;        // local row within half
#pragma unroll
                for (int j = 0; j < 3; j++) {
                    int c0 = wn * 24 + j * 8 + 2 * lk;
                    float b0 = bh[n0 + c0], b1 = bh[n0 + c0 + 1];
                    ghs[r0 * 100 + c0]           = acc[i][j][0] + b0;
                    ghs[r0 * 100 + c0 + 1]       = acc[i][j][1] + b1;
                    ghs[(r0 + 8) * 100 + c0]     = acc[i][j][2] + b0;
                    ghs[(r0 + 8) * 100 + c0 + 1] = acc[i][j][3] + b1;
                }
            }
        }
        __syncthreads();
#pragma unroll
        for (int it = 0; it < 8; it++) {
            int e = tid + it * 256;          // 2048 = 64 rows x 32 d
            int rr_ = e >> 5, ld = e & 31;
            int b = m0 + half * 64 + rr_;
            int d = d0 + ld;
            const float* gp = gi + ((long)b * VV + v) * 768 + 3 * d;
            float ghr = ghs[rr_ * 100 + 3 * ld];
            float ghz = ghs[rr_ * 100 + 3 * ld + 1];
            float ghn = ghs[rr_ * 100 + 3 * ld + 2];
            float r  = sigm(gp[0] + ghr);
            float zz = sigm(gp[1] + ghz);
            float nn = tanhf(gp[2] + r * ghn);
            float hold = hin[(long)b * 256 + d];
            float hnew = (1.0f - zz) * nn + zz * hold;
            hout[(long)b * 256 + d] = hnew;
            if (last) Hr[(long)b * 768 + z * 256 + d] = fmaxf(hnew, 0.0f);
        }
        __syncthreads();
    }
}

// ---------------- GRU gate 0 (h=0 -> gh = bhh), permuted layout ----------------
__global__ void gate0_kernel(const float* __restrict__ gi, const float* __restrict__ bhhp,
                             float* __restrict__ h)
{
    int idx = blockIdx.x * 256 + threadIdx.x;
    int z = idx >> 18;
    int rem = idx & 262143;
    int b = rem >> 8;
    int d = rem & 255;
    const float* girow = gi + ((long)z * 8192 + (long)b * VV) * 768 + 3 * d;
    const float* bh = bhhp + (long)z * 768 + 3 * d;
    float rr = sigm(girow[0] + bh[0]);
    float zz = sigm(girow[1] + bh[1]);
    float nn = tanhf(girow[2] + rr * bh[2]);
    h[idx] = (1.0f - zz) * nn;
}

__global__ void final1_kernel(const float* __restrict__ scorepad,
                              const float* __restrict__ ddi,
                              float* __restrict__ out, float* __restrict__ partials)
{
    __shared__ float p[VOC_M];
    __shared__ float red[256];
    int b = blockIdx.x, tid = threadIdx.x;
    if (tid < VOC_M) {
        float s = scorepad[(long)b * 256 + tid];
        out[(long)b * VOC_M + tid] = s;
        p[tid] = sigm(s);
    }
    __syncthreads();
    float part = 0.0f;
    if (tid < VOC_M) {
        float inner = 0.0f;
        for (int i = 0; i < VOC_M; i++) inner += p[i] * ddi[(long)i * VOC_M + tid];
        part = p[tid] * inner;
    }
    red[tid] = part;
    __syncthreads();
    for (int s = 128; s > 0; s >>= 1) {
        if (tid < s) red[tid] += red[tid + s];
        __syncthreads();
    }
    if (tid == 0) partials[b] = red[0];
}

__global__ void final2_kernel(const float* __restrict__ partials,
                              float* __restrict__ out, int out_size)
{
    __shared__ float red[256];
    int tid = threadIdx.x;
    float s = partials[tid] + partials[tid + 256] + partials[tid + 512] + partials[tid + 768];
    red[tid] = s;
    __syncthreads();
    for (int st = 128; st > 0; st >>= 1) {
        if (tid < st) red[tid] += red[tid + st];
        __syncthreads();
    }
    if (tid == 0 && out_size > BB * VOC_M) out[BB * VOC_M] = 0.0005f * red[0];
}

// ---------------- host launch ----------------
extern "C" void kernel_launch(void* const* d_in, const int* in_sizes, int n_in,
                              void* d_out, int out_size)
{
    const int* idx_diag = (const int*)d_in[0];
    const int* idx_proc = (const int*)d_in[1];
    const int* idx_med  = (const int*)d_in[2];
    const float* adj_diag = (const float*)d_in[3];
    const float* adj_proc = (const float*)d_in[4];
    const float* adj_med  = (const float*)d_in[5];
    const float* w_dm = (const float*)d_in[6];
    const float* w_pm = (const float*)d_in[7];
    const float* E_diag = (const float*)d_in[8];
    const float* E_proc = (const float*)d_in[9];
    const float* E_med  = (const float*)d_in[10];
    const float* W_homo = (const float*)d_in[11];
    const float* Wh_d  = (const float*)d_in[12];
    const float* Wh_p  = (const float*)d_in[13];
    const float* Wh_md = (const float*)d_in[14];
    const float* Wh_mp = (const float*)d_in[15];
    const float* rho   = (const float*)d_in[16];
    const float* gru_wih = (const float*)d_in[17];
    const float* gru_whh = (const float*)d_in[18];
    const float* gru_bih = (const float*)d_in[19];
    const float* gru_bhh = (const float*)d_in[20];
    const float* Wq = (const float*)d_in[21];
    const float* bq = (const float*)d_in[22];
    const float* ddi = (const float*)d_in[23];

    void* sp = nullptr;
    cudaGetSymbolAddress(&sp, g_scratch);
    float* S = (float*)sp;

    float* HEd   = S + OFF_HED;
    float* HEp   = S + OFF_HEP;
    float* HEm   = S + OFF_HEM;
    float* Temd  = S + OFF_TEMD;
    float* Temp_ = S + OFF_TEMP;
    float* Tedm  = S + OFF_TEDM;
    float* Tepm  = S + OFF_TEPM;
    float* seq   = S + OFF_SEQ;
    float* gi    = S + OFF_GI;
    float* h0    = S + OFF_H0;
    float* h1    = S + OFF_H1;
    float* Hr    = S + OFF_HR;
    float* Wq2p  = S + OFF_WQ2;
    float* bqp   = S + OFF_BQP;
    float* spad  = S + OFF_SP;
    float* part  = S + OFF_PART;
    float* WIHP  = S + OFF_WIHP;
    float* WHHP  = S + OFF_WHHP;
    float* BIHP  = S + OFF_BIHP;
    float* BHHP  = S + OFF_BHHP;

    // 1) tables + wq2 + weight permutes
    tables_kernel<<<1010, 256>>>(E_diag, E_proc, E_med, W_homo, Wh_d, Wh_p, Wh_md, Wh_mp,
                                 Wq, bq, gru_wih, gru_whh, gru_bih, gru_bhh,
                                 HEd, HEp, HEm, Temd, Temp_, Tedm, Tepm, Wq2p, bqp,
                                 WIHP, WHHP, BIHP, BHHP);

    // 2) fused per-visit graph kernel
    graph_kernel<<<BB * VV, 256>>>(idx_diag, idx_proc, idx_med,
                                   adj_diag, adj_proc, adj_med, w_dm, w_pm, rho,
                                   HEd, HEp, HEm, Temd, Temp_, Tedm, Tepm, seq);

    // 3) gi = seq @ wihp^T + bihp  (gate-interleaved columns)
    tgemm_tn<<<dim3(6, 64, 3), 256>>>(seq, 8192L * 256, WIHP, 768L * 256,
                                      BIHP, 768, gi, 8192L * 768,
                                      8192, 768, 256);

    // 4) GRU recurrence: step 0 specialized, steps 1..7 fused GEMM+gate, ping-pong h
    gate0_kernel<<<3072, 256>>>(gi, BHHP, h0);
    float* hb[2] = {h0, h1};
    for (int v = 1; v < VV; v++) {
        gru_step<<<dim3(8, 8, 3), 256>>>(hb[(v - 1) & 1], WHHP, BHHP, gi,
                                         hb[v & 1], v, Hr, v == VV - 1);
    }

    // 5) final score GEMM
    tgemm_tn<<<dim3(2, 8, 1), 256>>>(Hr, 0, Wq2p, 0, bqp, 0, spad, 0,
                                     1024, 256, 768);

    // 6) outputs
    final1_kernel<<<BB, 256>>>(spad, ddi, (float*)d_out, part);
    final2_kernel<<<1, 256>>>(part, (float*)d_out, out_size);
}

// round 8
// speedup vs baseline: 2.4816x; 1.0827x over previous
#include <cuda_runtime.h>
#include <cstdint>

#define BB 1024
#define VV 8
#define NDm 32
#define NPm 16
#define NMm 24
#define DD 256
#define VOC_D 2000
#define VOC_P 1500
#define VOC_M 131

// ---------------- scratch layout (floats) ----------------
#define OFF_HED   0L
#define OFF_HEP   512000L
#define OFF_HEM   896000L
#define OFF_TEMD  929536L
#define OFF_TEMP  963072L
#define OFF_TEDM  996608L
#define OFF_TEPM  1508608L
#define OFF_SEQ   1892608L        // [3][8192][256]
#define OFF_GI    8184064L        // [3][8192][768]
#define OFF_H0    27058432L       // [3][1024][256]
#define OFF_H1    27844864L       // [3][1024][256]
#define OFF_HR    28631296L       // [1024][768]
#define OFF_WQ2   29417728L       // [256][768]
#define OFF_BQP   29614336L       // [256]
#define OFF_SP    29614592L       // [1024][256]
#define OFF_PART  29876736L       // [1024]
#define OFF_WIHP  29877760L       // [3][768][256] permuted
#define OFF_WHHP  30467584L       // [3][768][256] permuted
#define OFF_BIHP  31057408L       // [3][768]
#define OFF_BHHP  31059712L       // [3][768]
#define SCRATCH_TOTAL 31062016L

__device__ __align__(256) float g_scratch[SCRATCH_TOTAL];

__device__ __forceinline__ float sigm(float x) { return 1.0f / (1.0f + expf(-x)); }
__device__ __forceinline__ uint32_t f2tf32(float x) {
    uint32_t r;
    asm("cvt.rna.tf32.f32 %0, %1;" : "=r"(r) : "f"(x));
    return r;
}
__device__ __forceinline__ void cpa16(float* smem, const float* g) {
    uint32_t s = (uint32_t)__cvta_generic_to_shared(smem);
    asm volatile("cp.async.ca.shared.global [%0], [%1], 16;" :: "r"(s), "l"(g));
}
__device__ __forceinline__ void cpa_commit() {
    asm volatile("cp.async.commit_group;");
}

// ---------------- Fused precompute: 7 table jobs + Wq2 + GRU weight permutes ----
// [0,465) tables | [465,721) wq2 | [721,1009) wih/whh permute | [1009,1010) biases
__global__ __launch_bounds__(256) void tables_kernel(
    const float* __restrict__ E_diag, const float* __restrict__ E_proc,
    const float* __restrict__ E_med,  const float* __restrict__ W_homo,
    const float* __restrict__ Wh_d,   const float* __restrict__ Wh_p,
    const float* __restrict__ Wh_md,  const float* __restrict__ Wh_mp,
    const float* __restrict__ Wq,     const float* __restrict__ bq,
    const float* __restrict__ gru_wih, const float* __restrict__ gru_whh,
    const float* __restrict__ gru_bih, const float* __restrict__ gru_bhh,
    float* __restrict__ HEd, float* __restrict__ HEp, float* __restrict__ HEm,
    float* __restrict__ Temd, float* __restrict__ Temp_,
    float* __restrict__ Tedm, float* __restrict__ Tepm,
    float* __restrict__ Wq2p, float* __restrict__ bqp,
    float* __restrict__ WIHP, float* __restrict__ WHHP,
    float* __restrict__ BIHP, float* __restrict__ BHHP)
{
    int blk = blockIdx.x;
    int tid = threadIdx.x;

    if (blk >= 1009) {                        // ---- bias permutes ----
        for (int e = tid; e < 2304; e += 256) {
            int z = e / 768, np = e % 768, d = np / 3, g = np % 3;
            BIHP[e] = gru_bih[(long)z * 768 + g * 256 + d];
            BHHP[e] = gru_bhh[(long)z * 768 + g * 256 + d];
        }
        return;
    }
    if (blk >= 721) {                         // ---- weight permutes ----
        int k = blk - 721;                    // 0..287, 16 rows each
        for (int i = 0; i < 16; i++) {
            int gr = k * 16 + i;              // 0..4607
            int t = gr / 2304;
            int rr = gr % 2304;
            int z = rr / 768, np = rr % 768, d = np / 3, g = np % 3;
            const float* src;
            float* dst;
            if (t == 0) {
                src = gru_wih + ((long)z * 768 + g * 256 + d) * 256;
                dst = WIHP + ((long)z * 768 + np) * 256;
            } else {
                src = gru_whh + ((long)z * 768 + g * 256 + d) * 256;
                dst = WHHP + ((long)z * 768 + np) * 256;
            }
            dst[tid] = src[tid];
        }
        return;
    }
    if (blk >= 465) {                         // ---- Wq2 fold ----
        int j = blk - 465;
        for (int c = tid; c < 768; c += 256) {
            float v = 0.0f;
            if (j < VOC_M) v = Wq[(long)j * 1536 + c] + Wq[(long)j * 1536 + 768 + c];
            Wq2p[(long)j * 768 + c] = v;
        }
        if (tid == 0) bqp[j] = (j < VOC_M) ? bq[j] : 0.0f;
        return;
    }

    const float* E; const float* W; float* dst; int rows; int r0;
    if (blk < 125)      { E = E_diag; W = W_homo;          dst = HEd;   rows = VOC_D; r0 = blk * 16; }
    else if (blk < 219) { E = E_proc; W = W_homo + 65536;  dst = HEp;   rows = VOC_P; r0 = (blk-125)*16; }
    else if (blk < 228) { E = E_med;  W = W_homo + 131072; dst = HEm;   rows = VOC_M; r0 = (blk-219)*16; }
    else if (blk < 237) { E = E_med;  W = Wh_d;            dst = Temd;  rows = VOC_M; r0 = (blk-228)*16; }
    else if (blk < 246) { E = E_med;  W = Wh_p;            dst = Temp_; rows = VOC_M; r0 = (blk-237)*16; }
    else if (blk < 371) { E = E_diag; W = Wh_md;           dst = Tedm;  rows = VOC_D; r0 = (blk-246)*16; }
    else                { E = E_proc; W = Wh_mp;           dst = Tepm;  rows = VOC_P; r0 = (blk-371)*16; }

    __shared__ __align__(16) float e[16][DD];
    for (int i = tid; i < 16 * (DD / 4); i += 256) {
        int rr = i >> 6;
        int cc = (i & 63) << 2;
        float4 v = make_float4(0.f, 0.f, 0.f, 0.f);
        if (r0 + rr < rows) v = *(const float4*)&E[(long)(r0 + rr) * DD + cc];
        *(float4*)&e[rr][cc] = v;
    }
    __syncthreads();

    float acc[16];
#pragma unroll
    for (int i = 0; i < 16; i++) acc[i] = 0.0f;
#pragma unroll 4
    for (int k = 0; k < DD; k++) {
        float w = W[(long)k * DD + tid];
#pragma unroll
        for (int i = 0; i < 16; i++) acc[i] += e[i][k] * w;
    }
#pragma unroll
    for (int i = 0; i < 16; i++)
        if (r0 + i < rows) dst[(long)(r0 + i) * DD + tid] = acc[i];
}

// ---------------- per-(b,v) fused graph kernel ----------------
#define HP 260

// Gram via tf32 mma + warp-parallel masked softmax with fused column-sum.
__device__ float homo_phase(const float* __restrict__ table, const int* sidx,
                            const float* __restrict__ adjg, int N,
                            float* hbuf, float* Sbuf, float* pbuf, float* csm, int tid)
{
    // vectorized gather of h rows
    for (int i = tid; i < N * 64; i += 256) {
        int r = i >> 6, c4 = (i & 63) << 2;
        *(float4*)&hbuf[r * HP + c4] = *(const float4*)&table[(long)sidx[r] * DD + c4];
    }
    __syncthreads();

    int warp = tid >> 5, l = tid & 31;

    // S = h h^T / 16 via mma.m16n8k8 tf32; one 16x8 tile per warp
    int tn_n = (N + 7) >> 3;
    int ntiles = ((N + 15) >> 4) * tn_n;
    if (warp < ntiles) {
        int wm = warp / tn_n, wn = warp % tn_n;
        int lq = l >> 2, lk = l & 3;
        const float* Ab = &hbuf[(wm * 16 + lq) * HP + lk];
        const float* Bb = &hbuf[(wn * 8 + lq) * HP + lk];
        float c0 = 0.f, c1 = 0.f, c2 = 0.f, c3 = 0.f;
#pragma unroll 4
        for (int k = 0; k < DD; k += 8) {
            uint32_t a0 = f2tf32(Ab[k]);
            uint32_t a1 = f2tf32(Ab[8 * HP + k]);
            uint32_t a2 = f2tf32(Ab[k + 4]);
            uint32_t a3 = f2tf32(Ab[8 * HP + k + 4]);
            uint32_t b0 = f2tf32(Bb[k]);
            uint32_t b1 = f2tf32(Bb[k + 4]);
            asm volatile(
                "mma.sync.aligned.m16n8k8.row.col.f32.tf32.tf32.f32 "
                "{%0,%1,%2,%3}, {%4,%5,%6,%7}, {%8,%9}, {%0,%1,%2,%3};"
                : "+f"(c0), "+f"(c1), "+f"(c2), "+f"(c3)
                : "r"(a0), "r"(a1), "r"(a2), "r"(a3), "r"(b0), "r"(b1));
        }
        int r0 = wm * 16 + lq, cc = wn * 8 + 2 * lk;
        Sbuf[r0 * 33 + cc]           = c0 * 0.0625f;
        Sbuf[r0 * 33 + cc + 1]       = c1 * 0.0625f;
        Sbuf[(r0 + 8) * 33 + cc]     = c2 * 0.0625f;
        Sbuf[(r0 + 8) * 33 + cc + 1] = c3 * 0.0625f;
    }
    __syncthreads();

    // warp-parallel masked softmax; only column sums are retained
    int rpw = N >> 3;                         // rows per warp: 4/2/3
    float colacc = 0.0f;
    for (int i = 0; i < rpw; i++) {
        int n = warp * rpw + i;
        float a = (l < N) ? adjg[n * N + l] : 0.0f;
        bool ok = (l < N) && ((a > 0.5f) || (l == n));
        float s = ok ? Sbuf[n * 33 + l] : -1e30f;
        float mx = s;
#pragma unroll
        for (int o = 16; o; o >>= 1) mx = fmaxf(mx, __shfl_xor_sync(0xffffffffu, mx, o));
        float e = ok ? expf(s - mx) : 0.0f;
        float sum = e;
#pragma unroll
        for (int o = 16; o; o >>= 1) sum += __shfl_xor_sync(0xffffffffu, sum, o);
        colacc += e / sum;
    }
    pbuf[warp * 33 + l] = colacc;
    __syncthreads();
    if (tid < 32) {
        float c = 0.0f;
#pragma unroll
        for (int w = 0; w < 8; w++) c += pbuf[w * 33 + tid];
        csm[tid] = c;
    }
    __syncthreads();

    // out[d] = sum_m c[m] * h[m][d]
    float o = 0.0f;
    for (int m = 0; m < N; m++) o += csm[m] * hbuf[m * HP + tid];
    __syncthreads();
    return o;
}

__global__ __launch_bounds__(256) void graph_kernel(
    const int* __restrict__ idx_diag, const int* __restrict__ idx_proc,
    const int* __restrict__ idx_med,
    const float* __restrict__ adj_diag, const float* __restrict__ adj_proc,
    const float* __restrict__ adj_med,
    const float* __restrict__ w_dm, const float* __restrict__ w_pm,
    const float* __restrict__ rho,
    const float* __restrict__ HEd, const float* __restrict__ HEp,
    const float* __restrict__ HEm,
    const float* __restrict__ Temd, const float* __restrict__ Temp_,
    const float* __restrict__ Tedm, const float* __restrict__ Tepm,
    float* __restrict__ seq)
{
    __shared__ __align__(16) float hbuf[NDm * HP];
    __shared__ float Sbuf[NDm * 33];
    __shared__ float pbuf[8 * 33];
    __shared__ float wdm[NDm * NMm];
    __shared__ float wpm[NPm * NMm];
    __shared__ float csm[NDm];
    __shared__ float gd[NMm], gp[NMm], fd[NDm], fp[NPm];
    __shared__ float rsd[NDm], csd[NMm], rsp[NPm], csp[NMm];
    __shared__ int sidx_d[NDm], sidx_p[NPm], sidx_m[NMm];
    __shared__ float srho[6];

    int tid = threadIdx.x;
    int row = blockIdx.x;
    int v = row % VV;

    if (tid < NDm) sidx_d[tid] = idx_diag[(long)row * NDm + tid];
    if (tid < NPm) sidx_p[tid] = idx_proc[(long)row * NPm + tid];
    if (tid < NMm) sidx_m[tid] = (v > 0) ? idx_med[(long)(row - 1) * NMm + tid] : 0;
    if (tid < 6) srho[tid] = rho[tid];
    __syncthreads();

    float od_ = homo_phase(HEd, sidx_d, adj_diag + (long)row * NDm * NDm, NDm,
                           hbuf, Sbuf, pbuf, csm, tid);
    float op_ = homo_phase(HEp, sidx_p, adj_proc + (long)row * NPm * NPm, NPm,
                           hbuf, Sbuf, pbuf, csm, tid);
    float om_ = 0.0f, hd2 = 0.0f, hp2 = 0.0f, hm2 = 0.0f;

    if (v > 0) {
        om_ = homo_phase(HEm, sidx_m, adj_med + (long)row * NMm * NMm, NMm,
                         hbuf, Sbuf, pbuf, csm, tid);

        for (int i = tid; i < NDm * NMm; i += 256) wdm[i] = w_dm[(long)row * NDm * NMm + i];
        for (int i = tid; i < NPm * NMm; i += 256) wpm[i] = w_pm[(long)row * NPm * NMm + i];
        __syncthreads();

        if (tid < NDm) {
            float s = 0; for (int m = 0; m < NMm; m++) s += wdm[tid * NMm + m];
            rsd[tid] = s;
        }
        if (tid >= 32 && tid < 32 + NMm) {
            int m = tid - 32; float s = 0;
            for (int n = 0; n < NDm; n++) s += wdm[n * NMm + m];
            csd[m] = s;
        }
        if (tid >= 64 && tid < 64 + NPm) {
            int n = tid - 64; float s = 0;
            for (int m = 0; m < NMm; m++) s += wpm[n * NMm + m];
            rsp[n] = s;
        }
        if (tid >= 96 && tid < 96 + NMm) {
            int m = tid - 96; float s = 0;
            for (int n = 0; n < NPm; n++) s += wpm[n * NMm + m];
            csp[m] = s;
        }
        __syncthreads();

        if (tid < NMm) {
            float s = 0;
            for (int n = 0; n < NDm; n++) s += wdm[n * NMm + tid] / (rsd[n] + 1e-8f);
            gd[tid] = s;
        }
        if (tid >= 32 && tid < 32 + NDm) {
            int n = tid - 32; float s = 0;
            for (int m = 0; m < NMm; m++) s += wdm[n * NMm + m] / (csd[m] + 1e-8f);
            fd[n] = s;
        }
        if (tid >= 64 && tid < 64 + NMm) {
            int m = tid - 64; float s = 0;
            for (int n = 0; n < NPm; n++) s += wpm[n * NMm + m] / (rsp[n] + 1e-8f);
            gp[m] = s;
        }
        if (tid >= 96 && tid < 96 + NPm) {
            int n = tid - 96; float s = 0;
            for (int m = 0; m < NMm; m++) s += wpm[n * NMm + m] / (csp[m] + 1e-8f);
            fp[n] = s;
        }
        __syncthreads();

        for (int m = 0; m < NMm; m++) {
            long base = (long)sidx_m[m] * DD + tid;
            hd2 += gd[m] * Temd[base];
            hp2 += gp[m] * Temp_[base];
        }
        for (int n = 0; n < NDm; n++) hm2 += fd[n] * Tedm[(long)sidx_d[n] * DD + tid];
        for (int n = 0; n < NPm; n++) hm2 += fp[n] * Tepm[(long)sidx_p[n] * DD + tid];
    }

    long o = (long)row * DD + tid;
    seq[o]                 = srho[0] * od_ + srho[1] * hd2;
    seq[2097152L + o]      = srho[2] * op_ + srho[3] * hp2;
    seq[2L * 2097152L + o] = srho[4] * om_ + srho[5] * hm2;
}

// ---------------- TF32 tensor-core GEMM (TN), cp.async 2-stage pipeline -------
// BK=16, smem stride 20 (conflict-free scalar fragment loads).
#define TS2 20

__global__ __launch_bounds__(256, 2) void tgemm_tn(
    const float* __restrict__ A, long Az,
    const float* __restrict__ Bm, long Bz,
    const float* __restrict__ bias, long biasz,
    float* __restrict__ C, long Cz,
    int M, int N, int K)
{
    A += (long)blockIdx.z * Az;
    Bm += (long)blockIdx.z * Bz;
    C += (long)blockIdx.z * Cz;
    const float* bi = bias + (long)blockIdx.z * biasz;

    __shared__ __align__(16) float As[2][128 * TS2];
    __shared__ __align__(16) float Bs[2][128 * TS2];

    int tid = threadIdx.x;
    int warp = tid >> 5, l = tid & 31;
    int wm = warp >> 2, wn = warp & 3;
    int m0 = blockIdx.y * 128, n0 = blockIdx.x * 128;

    // copy mapping: 512 16B-chunks per matrix per tile; 2 chunks/thread/matrix
    int c0r = tid >> 2, c0c = (tid & 3) * 4;         // chunk set 0: rows 0..63
    int c1r = 64 + (tid >> 2), c1c = (tid & 3) * 4;  // chunk set 1: rows 64..127

    const float* Ag = A + (long)m0 * K;
    const float* Bg = Bm + (long)n0 * K;

    float acc[4][4][4];
#pragma unroll
    for (int i = 0; i < 4; i++)
#pragma unroll
        for (int j = 0; j < 4; j++)
#pragma unroll
            for (int c = 0; c < 4; c++) acc[i][j][c] = 0.0f;

    int lq = l >> 2;
    int lk = l & 3;
    int T = K >> 4;

    // prologue: tile 0 -> buf 0
    cpa16(&As[0][c0r * TS2 + c0c], Ag + (long)c0r * K + c0c);
    cpa16(&As[0][c1r * TS2 + c1c], Ag + (long)c1r * K + c1c);
    cpa16(&Bs[0][c0r * TS2 + c0c], Bg + (long)c0r * K + c0c);
    cpa16(&Bs[0][c1r * TS2 + c1c], Bg + (long)c1r * K + c1c);
    cpa_commit();

    for (int t = 0; t < T; t++) {
        int cur = t & 1;
        if (t + 1 < T) {
            int nb = cur ^ 1;
            int ko = (t + 1) * 16;
            cpa16(&As[nb][c0r * TS2 + c0c], Ag + (long)c0r * K + ko + c0c);
            cpa16(&As[nb][c1r * TS2 + c1c], Ag + (long)c1r * K + ko + c1c);
            cpa16(&Bs[nb][c0r * TS2 + c0c], Bg + (long)c0r * K + ko + c0c);
            cpa16(&Bs[nb][c1r * TS2 + c1c], Bg + (long)c1r * K + ko + c1c);
            cpa_commit();
            asm volatile("cp.async.wait_group 1;");
        } else {
            asm volatile("cp.async.wait_group 0;");
        }
        __syncthreads();

#pragma unroll
        for (int kk = 0; kk < 16; kk += 8) {
            uint32_t af[4][4], bf[4][2];
#pragma unroll
            for (int i = 0; i < 4; i++) {
                int ar = wm * 64 + i * 16 + lq;
                af[i][0] = f2tf32(As[cur][ar * TS2 + kk + lk]);
                af[i][1] = f2tf32(As[cur][(ar + 8) * TS2 + kk + lk]);
                af[i][2] = f2tf32(As[cur][ar * TS2 + kk + lk + 4]);
                af[i][3] = f2tf32(As[cur][(ar + 8) * TS2 + kk + lk + 4]);
            }
#pragma unroll
            for (int j = 0; j < 4; j++) {
                int br = wn * 32 + j * 8 + lq;
                bf[j][0] = f2tf32(Bs[cur][br * TS2 + kk + lk]);
                bf[j][1] = f2tf32(Bs[cur][br * TS2 + kk + lk + 4]);
            }
#pragma unroll
            for (int i = 0; i < 4; i++)
#pragma unroll
                for (int j = 0; j < 4; j++) {
                    asm volatile(
                        "mma.sync.aligned.m16n8k8.row.col.f32.tf32.tf32.f32 "
                        "{%0,%1,%2,%3}, {%4,%5,%6,%7}, {%8,%9}, {%0,%1,%2,%3};"
                        : "+f"(acc[i][j][0]), "+f"(acc[i][j][1]),
                          "+f"(acc[i][j][2]), "+f"(acc[i][j][3])
                        : "r"(af[i][0]), "r"(af[i][1]), "r"(af[i][2]), "r"(af[i][3]),
                          "r"(bf[j][0]), "r"(bf[j][1]));
                }
        }
        __syncthreads();
    }

#pragma unroll
    for (int i = 0; i < 4; i++) {
        int r0 = m0 + wm * 64 + i * 16 + lq;
#pragma unroll
        for (int j = 0; j < 4; j++) {
            int cc0 = n0 + wn * 32 + j * 8 + 2 * lk;
            float b0 = bi[cc0], b1 = bi[cc0 + 1];
            *(float2*)&C[(long)r0 * N + cc0] =
                make_float2(acc[i][j][0] + b0, acc[i][j][1] + b1);
            *(float2*)&C[(long)(r0 + 8) * N + cc0] =
                make_float2(acc[i][j][2] + b0, acc[i][j][3] + b1);
        }
    }
}

// ---------------- fused GRU step: gh GEMM (gate-interleaved) + gates ----------
// grid (8, 8, 3): block = 128 batch rows x 96 gh cols (= 32 complete d-groups)
// cp.async 2-stage pipeline; gh staged in two 64-row halves in the smem union.
__global__ __launch_bounds__(256, 2) void gru_step(
    const float* __restrict__ hin, const float* __restrict__ whhp,
    const float* __restrict__ bhhp, const float* __restrict__ gi,
    float* __restrict__ hout, int v, float* __restrict__ Hr, int last)
{
    __shared__ __align__(16) float smu[2 * 128 * TS2 * 2];   // 40 KB
    float (*As)[128 * TS2] = (float (*)[128 * TS2])smu;
    float (*Bs)[128 * TS2] = (float (*)[128 * TS2])(smu + 2 * 128 * TS2);
    float* ghs = smu;                                        // 64*100 floats reused

    int z = blockIdx.z;
    hin  += (long)z * 262144;
    hout += (long)z * 262144;
    whhp += (long)z * 196608;
    const float* bh = bhhp + (long)z * 768;
    gi   += (long)z * 6291456;

    int tid = threadIdx.x;
    int warp = tid >> 5, l = tid & 31;
    int wm = warp >> 2, wn = warp & 3;
    int n0 = blockIdx.x * 96, m0 = blockIdx.y * 128;
    int d0 = blockIdx.x * 32;

    int c0r = tid >> 2, c0c = (tid & 3) * 4;
    int c1r = 64 + (tid >> 2), c1c = (tid & 3) * 4;

    const float* Ag = hin + (long)m0 * 256;
    const float* Bg = whhp + (long)n0 * 256;
    bool b0ok = c0r < 96;          // B has only 96 valid rows
    bool b1ok = c1r < 96;

    float acc[4][3][4];
#pragma unroll
    for (int i = 0; i < 4; i++)
#pragma unroll
        for (int j = 0; j < 3; j++)
#pragma unroll
            for (int c = 0; c < 4; c++) acc[i][j][c] = 0.0f;

    int lq = l >> 2, lk = l & 3;
    const int T = 16;              // K=256 / 16

    cpa16(&As[0][c0r * TS2 + c0c], Ag + (long)c0r * 256 + c0c);
    cpa16(&As[0][c1r * TS2 + c1c], Ag + (long)c1r * 256 + c1c);
    if (b0ok) cpa16(&Bs[0][c0r * TS2 + c0c], Bg + (long)c0r * 256 + c0c);
    if (b1ok) cpa16(&Bs[0][c1r * TS2 + c1c], Bg + (long)c1r * 256 + c1c);
    cpa_commit();

#pragma unroll 1
    for (int t = 0; t < T; t++) {
        int cur = t & 1;
        if (t + 1 < T) {
            int nb = cur ^ 1;
            int ko = (t + 1) * 16;
            cpa16(&As[nb][c0r * TS2 + c0c], Ag + (long)c0r * 256 + ko + c0c);
            cpa16(&As[nb][c1r * TS2 + c1c], Ag + (long)c1r * 256 + ko + c1c);
            if (b0ok) cpa16(&Bs[nb][c0r * TS2 + c0c], Bg + (long)c0r * 256 + ko + c0c);
            if (b1ok) cpa16(&Bs[nb][c1r * TS2 + c1c], Bg + (long)c1r * 256 + ko + c1c);
            cpa_commit();
            asm volatile("cp.async.wait_group 1;");
        } else {
            asm volatile("cp.async.wait_group 0;");
        }
        __syncthreads();

#pragma unroll
        for (int kk = 0; kk < 16; kk += 8) {
            uint32_t af[4][4], bf[3][2];
#pragma unroll
            for (int i = 0; i < 4; i++) {
                int ar = wm * 64 + i * 16 + lq;
                af[i][0] = f2tf32(As[cur][ar * TS2 + kk + lk]);
                af[i][1] = f2tf32(As[cur][(ar + 8) * TS2 + kk + lk]);
                af[i][2] = f2tf32(As[cur][ar * TS2 + kk + lk + 4]);
                af[i][3] = f2tf32(As[cur][(ar + 8) * TS2 + kk + lk + 4]);
            }
#pragma unroll
            for (int j = 0; j < 3; j++) {
                int br = wn * 24 + j * 8 + lq;
                bf[j][0] = f2tf32(Bs[cur][br * TS2 + kk + lk]);
                bf[j][1] = f2tf32(Bs[cur][br * TS2 + kk + lk + 4]);
            }
#pragma unroll
            for (int i = 0; i < 4; i++)
#pragma unroll
                for (int j = 0; j < 3; j++) {
                    asm volatile(
                        "mma.sync.aligned.m16n8k8.row.col.f32.tf32.tf32.f32 "
                        "{%0,%1,%2,%3}, {%4,%5,%6,%7}, {%8,%9}, {%0,%1,%2,%3};"
                        : "+f"(acc[i][j][0]), "+f"(acc[i][j][1]),
                          "+f"(acc[i][j][2]), "+f"(acc[i][j][3])
                        : "r"(af[i][0]), "r"(af[i][1]), "r"(af[i][2]), "r"(af[i][3]),
                          "r"(bf[j][0]), "r"(bf[j][1]));
                }
        }
        __syncthreads();
    }

    // two-half staging + gate application (rows [half*64, half*64+64))
#pragma unroll 1
    for (int half = 0; half < 2; half++) {
        if (wm == half) {
#pragma unroll
            for (int i = 0; i < 4; i++) {
                int r0 = i * 16 + lq;        // local row within half
#pragma unroll
                for (int j = 0; j < 3; j++) {
                    int cc0 = wn * 24 + j * 8 + 2 * lk;
                    float b0 = bh[n0 + cc0], b1 = bh[n0 + cc0 + 1];
                    ghs[r0 * 100 + cc0]           = acc[i][j][0] + b0;
                    ghs[r0 * 100 + cc0 + 1]       = acc[i][j][1] + b1;
                    ghs[(r0 + 8) * 100 + cc0]     = acc[i][j][2] + b0;
                    ghs[(r0 + 8) * 100 + cc0 + 1] = acc[i][j][3] + b1;
                }
            }
        }
        __syncthreads();
#pragma unroll
        for (int it = 0; it < 8; it++) {
            int e = tid + it * 256;          // 2048 = 64 rows x 32 d
            int rr_ = e >> 5, ld = e & 31;
            int b = m0 + half * 64 + rr_;
            int d = d0 + ld;
            const float* gp = gi + ((long)b * VV + v) * 768 + 3 * d;
            float ghr = ghs[rr_ * 100 + 3 * ld];
            float ghz = ghs[rr_ * 100 + 3 * ld + 1];
            float ghn = ghs[rr_ * 100 + 3 * ld + 2];
            float r  = sigm(gp[0] + ghr);
            float zz = sigm(gp[1] + ghz);
            float nn = tanhf(gp[2] + r * ghn);
            float hold = hin[(long)b * 256 + d];
            float hnew = (1.0f - zz) * nn + zz * hold;
            hout[(long)b * 256 + d] = hnew;
            if (last) Hr[(long)b * 768 + z * 256 + d] = fmaxf(hnew, 0.0f);
        }
        __syncthreads();
    }
}

// ---------------- GRU gate 0 (h=0 -> gh = bhh), permuted layout ----------------
__global__ void gate0_kernel(const float* __restrict__ gi, const float* __restrict__ bhhp,
                             float* __restrict__ h)
{
    int idx = blockIdx.x * 256 + threadIdx.x;
    int z = idx >> 18;
    int rem = idx & 262143;
    int b = rem >> 8;
    int d = rem & 255;
    const float* girow = gi + ((long)z * 8192 + (long)b * VV) * 768 + 3 * d;
    const float* bh = bhhp + (long)z * 768 + 3 * d;
    float rr = sigm(girow[0] + bh[0]);
    float zz = sigm(girow[1] + bh[1]);
    float nn = tanhf(girow[2] + rr * bh[2]);
    h[idx] = (1.0f - zz) * nn;
}

__global__ void final1_kernel(const float* __restrict__ scorepad,
                              const float* __restrict__ ddi,
                              float* __restrict__ out, float* __restrict__ partials)
{
    __shared__ float p[VOC_M];
    __shared__ float red[256];
    int b = blockIdx.x, tid = threadIdx.x;
    if (tid < VOC_M) {
        float s = scorepad[(long)b * 256 + tid];
        out[(long)b * VOC_M + tid] = s;
        p[tid] = sigm(s);
    }
    __syncthreads();
    float part = 0.0f;
    if (tid < VOC_M) {
        float inner = 0.0f;
        for (int i = 0; i < VOC_M; i++) inner += p[i] * ddi[(long)i * VOC_M + tid];
        part = p[tid] * inner;
    }
    red[tid] = part;
    __syncthreads();
    for (int s = 128; s > 0; s >>= 1) {
        if (tid < s) red[tid] += red[tid + s];
        __syncthreads();
    }
    if (tid == 0) partials[b] = red[0];
}

__global__ void final2_kernel(const float* __restrict__ partials,
                              float* __restrict__ out, int out_size)
{
    __shared__ float red[256];
    int tid = threadIdx.x;
    float s = partials[tid] + partials[tid + 256] + partials[tid + 512] + partials[tid + 768];
    red[tid] = s;
    __syncthreads();
    for (int st = 128; st > 0; st >>= 1) {
        if (tid < st) red[tid] += red[tid + st];
        __syncthreads();
    }
    if (tid == 0 && out_size > BB * VOC_M) out[BB * VOC_M] = 0.0005f * red[0];
}

// ---------------- host launch ----------------
extern "C" void kernel_launch(void* const* d_in, const int* in_sizes, int n_in,
                              void* d_out, int out_size)
{
    const int* idx_diag = (const int*)d_in[0];
    const int* idx_proc = (const int*)d_in[1];
    const int* idx_med  = (const int*)d_in[2];
    const float* adj_diag = (const float*)d_in[3];
    const float* adj_proc = (const float*)d_in[4];
    const float* adj_med  = (const float*)d_in[5];
    const float* w_dm = (const float*)d_in[6];
    const float* w_pm = (const float*)d_in[7];
    const float* E_diag = (const float*)d_in[8];
    const float* E_proc = (const float*)d_in[9];
    const float* E_med  = (const float*)d_in[10];
    const float* W_homo = (const float*)d_in[11];
    const float* Wh_d  = (const float*)d_in[12];
    const float* Wh_p  = (const float*)d_in[13];
    const float* Wh_md = (const float*)d_in[14];
    const float* Wh_mp = (const float*)d_in[15];
    const float* rho   = (const float*)d_in[16];
    const float* gru_wih = (const float*)d_in[17];
    const float* gru_whh = (const float*)d_in[18];
    const float* gru_bih = (const float*)d_in[19];
    const float* gru_bhh = (const float*)d_in[20];
    const float* Wq = (const float*)d_in[21];
    const float* bq = (const float*)d_in[22];
    const float* ddi = (const float*)d_in[23];

    void* sp = nullptr;
    cudaGetSymbolAddress(&sp, g_scratch);
    float* S = (float*)sp;

    float* HEd   = S + OFF_HED;
    float* HEp   = S + OFF_HEP;
    float* HEm   = S + OFF_HEM;
    float* Temd  = S + OFF_TEMD;
    float* Temp_ = S + OFF_TEMP;
    float* Tedm  = S + OFF_TEDM;
    float* Tepm  = S + OFF_TEPM;
    float* seq   = S + OFF_SEQ;
    float* gi    = S + OFF_GI;
    float* h0    = S + OFF_H0;
    float* h1    = S + OFF_H1;
    float* Hr    = S + OFF_HR;
    float* Wq2p  = S + OFF_WQ2;
    float* bqp   = S + OFF_BQP;
    float* spad  = S + OFF_SP;
    float* part  = S + OFF_PART;
    float* WIHP  = S + OFF_WIHP;
    float* WHHP  = S + OFF_WHHP;
    float* BIHP  = S + OFF_BIHP;
    float* BHHP  = S + OFF_BHHP;

    // 1) tables + wq2 + weight permutes
    tables_kernel<<<1010, 256>>>(E_diag, E_proc, E_med, W_homo, Wh_d, Wh_p, Wh_md, Wh_mp,
                                 Wq, bq, gru_wih, gru_whh, gru_bih, gru_bhh,
                                 HEd, HEp, HEm, Temd, Temp_, Tedm, Tepm, Wq2p, bqp,
                                 WIHP, WHHP, BIHP, BHHP);

    // 2) fused per-visit graph kernel
    graph_kernel<<<BB * VV, 256>>>(idx_diag, idx_proc, idx_med,
                                   adj_diag, adj_proc, adj_med, w_dm, w_pm, rho,
                                   HEd, HEp, HEm, Temd, Temp_, Tedm, Tepm, seq);

    // 3) gi = seq @ wihp^T + bihp  (gate-interleaved columns)
    tgemm_tn<<<dim3(6, 64, 3), 256>>>(seq, 8192L * 256, WIHP, 768L * 256,
                                      BIHP, 768, gi, 8192L * 768,
                                      8192, 768, 256);

    // 4) GRU recurrence: step 0 specialized, steps 1..7 fused GEMM+gate, ping-pong h
    gate0_kernel<<<3072, 256>>>(gi, BHHP, h0);
    float* hb[2] = {h0, h1};
    for (int v = 1; v < VV; v++) {
        gru_step<<<dim3(8, 8, 3), 256>>>(hb[(v - 1) & 1], WHHP, BHHP, gi,
                                         hb[v & 1], v, Hr, v == VV - 1);
    }

    // 5) final score GEMM
    tgemm_tn<<<dim3(2, 8, 1), 256>>>(Hr, 0, Wq2p, 0, bqp, 0, spad, 0,
                                     1024, 256, 768);

    // 6) outputs
    final1_kernel<<<BB, 256>>>(spad, ddi, (float*)d_out, part);
    final2_kernel<<<1, 256>>>(part, (float*)d_out, out_size);
}